// round 10
// baseline (speedup 1.0000x reference)
#include <cuda_runtime.h>

#define BB 8
#define AA 8
#define FF 512
#define HH 128
#define D  32
#define HID 256

// Row layout of fused node buffer X:
#define OFF_R  0
#define OFF_F  64
#define OFF_RH 4160
#define OFF_FH 5184
#define R_TOT  6208

#define FULL 0xffffffffu

// Static device scratch
__device__ __align__(16) float gX[R_TOT * D];
__device__ __align__(16) float gQ[R_TOT * D];
__device__ __align__(16) float gK[R_TOT * D];
__device__ __align__(16) float gV[R_TOT * D];
__device__ __align__(16) float gHk[2048 * HID];    // phase A y-side hidden (+eb1): rh [0,1024), fh [1024,2048)
__device__ __align__(16) float gYV[2048 * D];      // phase A y values
__device__ __align__(16) float gHkB[4096 * HID];   // phase B y-side (frontier)
__device__ __align__(16) float gYVB[4096 * D];
// phase-B split-softmax scratch
__device__ __align__(16) float gE[64 * 512];
__device__ float gM4[64 * 4];
__device__ float gS4[64 * 4];
__device__ __align__(16) float gPA[64 * 4 * 32];
__device__ int gCnt[192];   // 3 iterations x 64 rows, zeroed by k_init each replay

__device__ __forceinline__ float red32(float v) {
#pragma unroll
    for (int o = 16; o; o >>= 1) v += __shfl_xor_sync(FULL, v, o);
    return v;
}
__device__ __forceinline__ float rmax32(float v) {
#pragma unroll
    for (int o = 16; o; o >>= 1) v = fmaxf(v, __shfl_xor_sync(FULL, v, o));
    return v;
}
__device__ __forceinline__ float red8(float v) {
    v += __shfl_xor_sync(FULL, v, 1);
    v += __shfl_xor_sync(FULL, v, 2);
    v += __shfl_xor_sync(FULL, v, 4);
    return v;
}

// Butterfly-reduce 8 per-lane accumulators across all 32 lanes (9 shuffles).
__device__ __forceinline__ void bfly8(float (&a)[8], int l) {
    {
        bool hi = (l & 1);
#pragma unroll
        for (int k = 0; k < 4; ++k) {
            float send = hi ? a[k] : a[k + 4];
            float recv = __shfl_xor_sync(FULL, send, 1);
            a[k] = (hi ? a[k + 4] : a[k]) + recv;
        }
    }
    {
        bool hi = (l & 2);
#pragma unroll
        for (int k = 0; k < 2; ++k) {
            float send = hi ? a[k] : a[k + 2];
            float recv = __shfl_xor_sync(FULL, send, 2);
            a[k] = (hi ? a[k + 2] : a[k]) + recv;
        }
    }
    {
        bool hi = (l & 4);
        float send = hi ? a[0] : a[1];
        float recv = __shfl_xor_sync(FULL, send, 4);
        a[0] = (hi ? a[1] : a[0]) + recv;
    }
    a[0] += __shfl_xor_sync(FULL, a[0], 8);
    a[0] += __shfl_xor_sync(FULL, a[0], 16);
}
__device__ __forceinline__ int irev3(int l) {
    return ((l & 1) << 2) | (l & 2) | ((l >> 2) & 1);
}

// 8-term edge-MLP partial for one j over this lane's 8 d's
__device__ __forceinline__ float term8(const float4& hq0, const float4& hq1,
                                       const float4& a0, const float4& a1, float dij,
                                       const float4& wd0, const float4& wd1,
                                       const float4& e20, const float4& e21) {
    float acc;
    acc = fmaxf(fmaf(dij, wd0.x, hq0.x + a0.x), 0.f) * e20.x;
    acc = fmaf(fmaxf(fmaf(dij, wd0.y, hq0.y + a0.y), 0.f), e20.y, acc);
    acc = fmaf(fmaxf(fmaf(dij, wd0.z, hq0.z + a0.z), 0.f), e20.z, acc);
    acc = fmaf(fmaxf(fmaf(dij, wd0.w, hq0.w + a0.w), 0.f), e20.w, acc);
    acc = fmaf(fmaxf(fmaf(dij, wd1.x, hq1.x + a1.x), 0.f), e21.x, acc);
    acc = fmaf(fmaxf(fmaf(dij, wd1.y, hq1.y + a1.y), 0.f), e21.y, acc);
    acc = fmaf(fmaxf(fmaf(dij, wd1.z, hq1.z + a1.z), 0.f), e21.z, acc);
    acc = fmaf(fmaxf(fmaf(dij, wd1.w, hq1.w + a1.w), 0.f), e21.w, acc);
    return acc;
}

// ---------------------------------------------------------------------------
// Node-init MLP + b3=0 QKV, warp-per-row (8 rows per block) + counter reset
// ---------------------------------------------------------------------------
__global__ void __launch_bounds__(256) k_init(
    const float* __restrict__ ap, const float* __restrict__ fp,
    const float* __restrict__ pa, const float* __restrict__ pg,
    const float* __restrict__ W1, const float* __restrict__ b1,
    const float* __restrict__ W2, const float* __restrict__ b2,
    const float* __restrict__ Wq, const float* __restrict__ bq,
    const float* __restrict__ Wk, const float* __restrict__ bk,
    const float* __restrict__ Wv, const float* __restrict__ bv) {
    __shared__ float hw[8][256];
    int w = threadIdx.x >> 5, l = threadIdx.x & 31;
    if (blockIdx.x == 0 && threadIdx.x < 192) gCnt[threadIdx.x] = 0;
    int r = blockIdx.x * 8 + w;
    const float* src;
    if (r < OFF_F)        src = ap + r * 3;
    else if (r < OFF_RH)  src = fp + (r - OFF_F) * 3;
    else if (r < OFF_FH)  src = pa + (r - OFF_RH) * 3;
    else                  src = pg + (r - OFF_FH) * 3;
    float x0 = src[0], x1 = src[1], x2 = src[2];
#pragma unroll
    for (int u = 0; u < 8; ++u) {
        int d = u * 32 + l;
        float h = fmaf(x0, W1[d], fmaf(x1, W1[256 + d], fmaf(x2, W1[512 + d], b1[d])));
        hw[w][d] = fmaxf(h, 0.0f);
    }
    __syncwarp();
    float acc = b2[l];
#pragma unroll 8
    for (int j = 0; j < 256; ++j) acc = fmaf(hw[w][j], W2[j * 32 + l], acc);
    gX[r * 32 + l] = acc;
    // fused b3=0 QKV
    float aq = bq[l], ak = bk[l], av = bv[l];
#pragma unroll
    for (int c = 0; c < 32; ++c) {
        float xb = __shfl_sync(FULL, acc, c);
        aq = fmaf(xb, Wq[c * 32 + l], aq);
        ak = fmaf(xb, Wk[c * 32 + l], ak);
        av = fmaf(xb, Wv[c * 32 + l], av);
    }
    gQ[r * 32 + l] = aq; gK[r * 32 + l] = ak; gV[r * 32 + l] = av;
}

// ---------------------------------------------------------------------------
// Intra attention, TI=8 rows per block, + fused y-side prep for rh/fh rows
// + next-iteration QKV for rh/fh rows. Score LDG pipelined; agg unrolled x2.
// blocks: [0,8) robot  [8,520) frontier  [520,648) rh  [648,776) fh
// ---------------------------------------------------------------------------
__global__ void __launch_bounds__(256) k_intra(
    const float* __restrict__ nW1, const float* __restrict__ nb1,
    const float* __restrict__ nW2, const float* __restrict__ nb2,
    const float* __restrict__ Wk, const float* __restrict__ bk,
    const float* __restrict__ Wv, const float* __restrict__ bv,
    const float* __restrict__ eW1, const float* __restrict__ eb1,
    const float* __restrict__ WqN, const float* __restrict__ bqN,
    const float* __restrict__ WkN, const float* __restrict__ bkN,
    const float* __restrict__ WvN, const float* __restrict__ bvN) {
    __shared__ __align__(16) float qs[8][32];
    __shared__ float sc[8][512];
    __shared__ float partA[8][8][32];
    __shared__ __align__(16) float xa[64][8];
    __shared__ float hh[8][256];
    __shared__ float inv[8];

    int t = threadIdx.x, w = t >> 5, l = t & 31;
    int blk = blockIdx.x;
    int base, N, r0;
    if (blk < 8)        { base = blk * 8; N = 8; r0 = base; }
    else if (blk < 520) { int f = blk - 8;   int b = f >> 6, tl = f & 63; base = OFF_F  + b * 512; N = 512; r0 = base + tl * 8; }
    else if (blk < 648) { int g = blk - 520; int b = g >> 4, tl = g & 15; base = OFF_RH + b * 128; N = 128; r0 = base + tl * 8; }
    else                { int g = blk - 648; int b = g >> 4, tl = g & 15; base = OFF_FH + b * 128; N = 128; r0 = base + tl * 8; }

    qs[w][l] = gQ[(r0 + w) * 32 + l];
    __syncthreads();

    // scores: subwarp-8 groups, 4 j per warp in flight, k4 load pipelined
    int sl = l & 7, slot = w * 4 + (l >> 3);
    {
        float4 k4 = (slot < N) ? *(const float4*)(gK + (base + slot) * 32 + sl * 4)
                               : make_float4(0.f, 0.f, 0.f, 0.f);
        for (int jj = slot; jj < N; jj += 32) {
            float4 nk4;
            if (jj + 32 < N) nk4 = *(const float4*)(gK + (base + jj + 32) * 32 + sl * 4);
#pragma unroll
            for (int i = 0; i < 8; ++i) {
                float4 q4 = *(const float4*)&qs[i][sl * 4];
                float acc = q4.x * k4.x + q4.y * k4.y + q4.z * k4.z + q4.w * k4.w;
                acc = red8(acc);
                if (sl == 0) sc[i][jj] = acc;
            }
            k4 = nk4;
        }
    }
    __syncthreads();

    // softmax: warp-per-i
    {
        int i = w;
        float m = -1e30f;
        for (int j = l; j < N; j += 32) m = fmaxf(m, sc[i][j]);
        m = rmax32(m);
        float s = 0.0f;
        for (int j = l; j < N; j += 32) { float e = __expf(sc[i][j] - m); sc[i][j] = e; s += e; }
        s = red32(s);
        if (l == 0) inv[i] = 1.0f / s;
    }
    __syncthreads();

    // agg: warps split j, 8 accumulators, unrolled x2 with batched loads
    {
        float ac[8];
#pragma unroll
        for (int i = 0; i < 8; ++i) ac[i] = 0.0f;
        for (int j = w; j < N; j += 16) {
            float v0 = gV[(base + j) * 32 + l];
            bool has1 = (j + 8 < N);
            float v1 = has1 ? gV[(base + j + 8) * 32 + l] : 0.0f;
#pragma unroll
            for (int i = 0; i < 8; ++i) {
                ac[i] = fmaf(sc[i][j], v0, ac[i]);
                if (has1) ac[i] = fmaf(sc[i][j + 8], v1, ac[i]);
            }
        }
#pragma unroll
        for (int i = 0; i < 8; ++i) partA[w][i][l] = ac[i];
    }
    __syncthreads();
    {
        int i = w;
        float s = 0.0f;
#pragma unroll
        for (int ww = 0; ww < 8; ++ww) s += partA[ww][i][l];
        xa[32 + l][i] = s * inv[i];
        xa[l][i] = gX[(r0 + i) * 32 + l];
    }
    __syncthreads();

    // node MLP stage1
    {
        float h8[8];
        float bb = nb1[t];
#pragma unroll
        for (int i = 0; i < 8; ++i) h8[i] = bb;
#pragma unroll 4
        for (int c = 0; c < 64; ++c) {
            float w1 = nW1[c * 256 + t];
            float4 a0 = *(const float4*)&xa[c][0];
            float4 a1 = *(const float4*)&xa[c][4];
            h8[0] = fmaf(a0.x, w1, h8[0]); h8[1] = fmaf(a0.y, w1, h8[1]);
            h8[2] = fmaf(a0.z, w1, h8[2]); h8[3] = fmaf(a0.w, w1, h8[3]);
            h8[4] = fmaf(a1.x, w1, h8[4]); h8[5] = fmaf(a1.y, w1, h8[5]);
            h8[6] = fmaf(a1.z, w1, h8[6]); h8[7] = fmaf(a1.w, w1, h8[7]);
        }
#pragma unroll
        for (int i = 0; i < 8; ++i) hh[i][t] = fmaxf(h8[i], 0.0f);
    }
    __syncthreads();

    // stage2: warp-per-i output + residual + fused y-prep + next-iter QKV
    {
        int i = w;
        float acc = nb2[l];
#pragma unroll 8
        for (int j = 0; j < 256; ++j) acc = fmaf(hh[i][j], nW2[j * 32 + l], acc);
        float xn = xa[l][i] + acc;
        int r = r0 + i;
        gX[r * 32 + l] = xn;
        if (r >= OFF_RH) {  // rh/fh rows: emit hk, yv for phase A + next QKV
            int hr = r - OFF_RH;
            float yk = bk[l], yv = bv[l];
            float aq = bqN[l], ak2 = bkN[l], av2 = bvN[l];
#pragma unroll
            for (int c = 0; c < 32; ++c) {
                float xb = __shfl_sync(FULL, xn, c);
                yk  = fmaf(xb, Wk[c * 32 + l], yk);
                yv  = fmaf(xb, Wv[c * 32 + l], yv);
                aq  = fmaf(xb, WqN[c * 32 + l], aq);
                ak2 = fmaf(xb, WkN[c * 32 + l], ak2);
                av2 = fmaf(xb, WvN[c * 32 + l], av2);
            }
            gYV[hr * 32 + l] = yv;
            gQ[r * 32 + l] = aq; gK[r * 32 + l] = ak2; gV[r * 32 + l] = av2;
            float hk[8];
#pragma unroll
            for (int u = 0; u < 8; ++u) hk[u] = eb1[u * 32 + l];
#pragma unroll
            for (int c = 0; c < 32; ++c) {
                float ykb = __shfl_sync(FULL, yk, c);
                const float* e1 = eW1 + (32 + c) * 256;
#pragma unroll
                for (int u = 0; u < 8; ++u) hk[u] = fmaf(ykb, e1[u * 32 + l], hk[u]);
            }
#pragma unroll
            for (int u = 0; u < 8; ++u) gHk[hr * 256 + u * 32 + l] = hk[u];
        }
    }
}

// ---------------------------------------------------------------------------
// Inter phase A (R7 config): j partitioned across warps, butterfly reduction,
// software-pipelined hk loads, 2 blocks/SM, dt transposed for float4 dj loads.
// + next-iter QKV for frontier rows.
// blocks: [0,8) robot-vs-rh  [8,520) frontier-vs-fh
// ---------------------------------------------------------------------------
__global__ void __launch_bounds__(256, 2) k_mainA(
    const float* __restrict__ disRP, const float* __restrict__ disFP,
    const float* __restrict__ Wq, const float* __restrict__ bq,
    const float* __restrict__ Wk, const float* __restrict__ bk,
    const float* __restrict__ Wv, const float* __restrict__ bv,
    const float* __restrict__ eW1, const float* __restrict__ eb1,
    const float* __restrict__ eW2,
    const float* __restrict__ nW1, const float* __restrict__ nb1,
    const float* __restrict__ nW2, const float* __restrict__ nb2,
    const float* __restrict__ WqN, const float* __restrict__ bqN,
    const float* __restrict__ WkN, const float* __restrict__ bkN,
    const float* __restrict__ WvN, const float* __restrict__ bvN) {
    __shared__ __align__(16) float hqs[8][256];
    __shared__ __align__(16) float dtT[128 * 8];   // [j][i]
    __shared__ float sc[8][128];
    __shared__ float partA[8][8][32];
    __shared__ __align__(16) float xa[64][8];
    __shared__ float hh[8][256];
    __shared__ float inv[8];

    int t = threadIdx.x, w = t >> 5, l = t & 31;
    int blk = blockIdx.x;
    int xrow0, hkbase, isF;
    const float* disrow;
    if (blk < 8) { xrow0 = blk * 8; hkbase = blk * 128; isF = 0; disrow = disRP + blk * 8 * 128; }
    else {
        int f = blk - 8; int b = f >> 6, tl = f & 63;
        xrow0 = OFF_F + b * 512 + tl * 8; hkbase = 1024 + b * 128; isF = 1;
        disrow = disFP + (b * 512 + tl * 8) * 128;
    }

    // x-side: xq = X@Wq+bq ; hq = xq@eW1[0:32]
    {
        float x = gX[(xrow0 + w) * 32 + l];
        float xq = bq[l];
#pragma unroll
        for (int c = 0; c < 32; ++c) xq = fmaf(__shfl_sync(FULL, x, c), Wq[c * 32 + l], xq);
        float hq[8];
#pragma unroll
        for (int u = 0; u < 8; ++u) hq[u] = 0.0f;
#pragma unroll
        for (int c = 0; c < 32; ++c) {
            float xqb = __shfl_sync(FULL, xq, c);
            const float* e1 = eW1 + c * 256;
#pragma unroll
            for (int u = 0; u < 8; ++u) hq[u] = fmaf(xqb, e1[u * 32 + l], hq[u]);
        }
#pragma unroll
        for (int u = 0; u < 8; ++u) hqs[w][u * 32 + l] = hq[u];
    }
    // transpose dis into dtT[j][i]
    for (int idx = t; idx < 1024; idx += 256) {
        int i = idx >> 7, j = idx & 127;
        dtT[j * 8 + i] = disrow[idx];
    }
    __syncthreads();

    float4 wd0 = *(const float4*)(eW1 + 64 * 256 + 4 * l);
    float4 wd1 = *(const float4*)(eW1 + 64 * 256 + 128 + 4 * l);
    float4 e20 = *(const float4*)(eW2 + 4 * l);
    float4 e21 = *(const float4*)(eW2 + 128 + 4 * l);

    // scores: warp w handles j in [16w, 16w+16); hk loads software-pipelined
    {
        const float4* hkp = (const float4*)(gHk + (size_t)hkbase * 256);
        int j0 = w * 16;
        float4 hk0 = hkp[(size_t)j0 * 64 + l];
        float4 hk1 = hkp[(size_t)j0 * 64 + 32 + l];
        for (int jj = 0; jj < 16; ++jj) {
            int j = j0 + jj;
            float4 nk0, nk1;
            if (jj < 15) {
                nk0 = hkp[(size_t)(j + 1) * 64 + l];
                nk1 = hkp[(size_t)(j + 1) * 64 + 32 + l];
            }
            float4 dj0 = *(const float4*)&dtT[j * 8];
            float4 dj1 = *(const float4*)&dtT[j * 8 + 4];
            float acc[8];
            {
                float4 hq0 = *(const float4*)&hqs[0][4 * l];
                float4 hq1 = *(const float4*)&hqs[0][128 + 4 * l];
                acc[0] = term8(hq0, hq1, hk0, hk1, dj0.x, wd0, wd1, e20, e21);
                hq0 = *(const float4*)&hqs[1][4 * l];
                hq1 = *(const float4*)&hqs[1][128 + 4 * l];
                acc[1] = term8(hq0, hq1, hk0, hk1, dj0.y, wd0, wd1, e20, e21);
                hq0 = *(const float4*)&hqs[2][4 * l];
                hq1 = *(const float4*)&hqs[2][128 + 4 * l];
                acc[2] = term8(hq0, hq1, hk0, hk1, dj0.z, wd0, wd1, e20, e21);
                hq0 = *(const float4*)&hqs[3][4 * l];
                hq1 = *(const float4*)&hqs[3][128 + 4 * l];
                acc[3] = term8(hq0, hq1, hk0, hk1, dj0.w, wd0, wd1, e20, e21);
                hq0 = *(const float4*)&hqs[4][4 * l];
                hq1 = *(const float4*)&hqs[4][128 + 4 * l];
                acc[4] = term8(hq0, hq1, hk0, hk1, dj1.x, wd0, wd1, e20, e21);
                hq0 = *(const float4*)&hqs[5][4 * l];
                hq1 = *(const float4*)&hqs[5][128 + 4 * l];
                acc[5] = term8(hq0, hq1, hk0, hk1, dj1.y, wd0, wd1, e20, e21);
                hq0 = *(const float4*)&hqs[6][4 * l];
                hq1 = *(const float4*)&hqs[6][128 + 4 * l];
                acc[6] = term8(hq0, hq1, hk0, hk1, dj1.z, wd0, wd1, e20, e21);
                hq0 = *(const float4*)&hqs[7][4 * l];
                hq1 = *(const float4*)&hqs[7][128 + 4 * l];
                acc[7] = term8(hq0, hq1, hk0, hk1, dj1.w, wd0, wd1, e20, e21);
            }
            bfly8(acc, l);
            if (l < 8) sc[irev3(l)][j] = acc[0];
            hk0 = nk0; hk1 = nk1;
        }
    }
    __syncthreads();

    // softmax warp-per-i
    {
        int i = w;
        float m = -1e30f;
#pragma unroll
        for (int k = 0; k < 4; ++k) m = fmaxf(m, sc[i][l + 32 * k]);
        m = rmax32(m);
        float s = 0.0f;
#pragma unroll
        for (int k = 0; k < 4; ++k) {
            float e = __expf(sc[i][l + 32 * k] - m);
            sc[i][l + 32 * k] = e; s += e;
        }
        s = red32(s);
        if (l == 0) inv[i] = 1.0f / s;
    }
    __syncthreads();

    // agg
    {
        float ac[8];
#pragma unroll
        for (int i = 0; i < 8; ++i) ac[i] = 0.0f;
        for (int j = w; j < 128; j += 16) {
            float v0 = gYV[(hkbase + j) * 32 + l];
            float v1 = gYV[(hkbase + j + 8) * 32 + l];
#pragma unroll
            for (int i = 0; i < 8; ++i) {
                ac[i] = fmaf(sc[i][j], v0, ac[i]);
                ac[i] = fmaf(sc[i][j + 8], v1, ac[i]);
            }
        }
#pragma unroll
        for (int i = 0; i < 8; ++i) partA[w][i][l] = ac[i];
    }
    __syncthreads();
    {
        int i = w;
        float s = 0.0f;
#pragma unroll
        for (int ww = 0; ww < 8; ++ww) s += partA[ww][i][l];
        xa[32 + l][i] = s * inv[i];
        xa[l][i] = gX[(xrow0 + i) * 32 + l];
    }
    __syncthreads();

    // node MLP stage1
    {
        float h8[8];
        float bb = nb1[t];
#pragma unroll
        for (int i = 0; i < 8; ++i) h8[i] = bb;
#pragma unroll 4
        for (int c = 0; c < 64; ++c) {
            float w1 = nW1[c * 256 + t];
            float4 a0 = *(const float4*)&xa[c][0];
            float4 a1 = *(const float4*)&xa[c][4];
            h8[0] = fmaf(a0.x, w1, h8[0]); h8[1] = fmaf(a0.y, w1, h8[1]);
            h8[2] = fmaf(a0.z, w1, h8[2]); h8[3] = fmaf(a0.w, w1, h8[3]);
            h8[4] = fmaf(a1.x, w1, h8[4]); h8[5] = fmaf(a1.y, w1, h8[5]);
            h8[6] = fmaf(a1.z, w1, h8[6]); h8[7] = fmaf(a1.w, w1, h8[7]);
        }
#pragma unroll
        for (int i = 0; i < 8; ++i) hh[i][t] = fmaxf(h8[i], 0.0f);
    }
    __syncthreads();

    // stage2 + phase-B prep + next-iter QKV for frontier rows
    {
        int i = w;
        float acc = nb2[l];
#pragma unroll 8
        for (int j = 0; j < 256; ++j) acc = fmaf(hh[i][j], nW2[j * 32 + l], acc);
        float xn = xa[l][i] + acc;
        int r = xrow0 + i;
        gX[r * 32 + l] = xn;
        if (isF) {
            int hr = r - OFF_F;
            float yk = bk[l], yv = bv[l];
            float aq = bqN[l], ak2 = bkN[l], av2 = bvN[l];
#pragma unroll
            for (int c = 0; c < 32; ++c) {
                float xb = __shfl_sync(FULL, xn, c);
                yk  = fmaf(xb, Wk[c * 32 + l], yk);
                yv  = fmaf(xb, Wv[c * 32 + l], yv);
                aq  = fmaf(xb, WqN[c * 32 + l], aq);
                ak2 = fmaf(xb, WkN[c * 32 + l], ak2);
                av2 = fmaf(xb, WvN[c * 32 + l], av2);
            }
            gYVB[hr * 32 + l] = yv;
            gQ[r * 32 + l] = aq; gK[r * 32 + l] = ak2; gV[r * 32 + l] = av2;
            float hk[8];
#pragma unroll
            for (int u = 0; u < 8; ++u) hk[u] = eb1[u * 32 + l];
#pragma unroll
            for (int c = 0; c < 32; ++c) {
                float ykb = __shfl_sync(FULL, yk, c);
                const float* e1 = eW1 + (32 + c) * 256;
#pragma unroll
                for (int u = 0; u < 8; ++u) hk[u] = fmaf(ykb, e1[u * 32 + l], hk[u]);
            }
#pragma unroll
            for (int u = 0; u < 8; ++u) gHkB[hr * 256 + u * 32 + l] = hk[u];
        }
    }
}

// ---------------------------------------------------------------------------
// Phase B: split softmax (grid = 64 rows x 4 chunks) with FUSED combine —
// last-arriving block per row does the old B2 work + robot next-iter QKV.
// ---------------------------------------------------------------------------
__global__ void __launch_bounds__(256) k_mainB1(
    const float* __restrict__ disRF,
    const float* __restrict__ Wq, const float* __restrict__ bq,
    const float* __restrict__ eW1, const float* __restrict__ eW2,
    const float* __restrict__ nW1, const float* __restrict__ nb1,
    const float* __restrict__ nW2, const float* __restrict__ nb2,
    const float* __restrict__ WqN, const float* __restrict__ bqN,
    const float* __restrict__ WkN, const float* __restrict__ bkN,
    const float* __restrict__ WvN, const float* __restrict__ bvN,
    float* edgeOut, int doMLP, int cntBase) {
    __shared__ __align__(16) float hqs[256];
    __shared__ float dt[128];
    __shared__ float sc[128];
    __shared__ float redv[8];
    __shared__ float part[256];
    __shared__ float fac[4];
    __shared__ float zz[64];
    __shared__ float hh[256];
    __shared__ int isLast;

    int t = threadIdx.x, w = t >> 5, l = t & 31;
    int row = blockIdx.x >> 2, c = blockIdx.x & 3;
    int b = row >> 3;
    int jbase = b * 512 + c * 128;

    // x-side hq
    {
        float x = gX[row * 32 + l];
        float xq = bq[l];
#pragma unroll
        for (int c2 = 0; c2 < 32; ++c2) xq = fmaf(__shfl_sync(FULL, x, c2), Wq[c2 * 32 + l], xq);
        float h = 0.0f;
#pragma unroll
        for (int c2 = 0; c2 < 32; ++c2)
            h = fmaf(__shfl_sync(FULL, xq, c2), eW1[c2 * 256 + w * 32 + l], h);
        hqs[w * 32 + l] = h;
    }
    if (t < 128) dt[t] = disRF[row * 512 + c * 128 + t];
    __syncthreads();

    float4 hq0 = *(const float4*)&hqs[4 * l];
    float4 hq1 = *(const float4*)&hqs[128 + 4 * l];
    float4 wd0 = *(const float4*)(eW1 + 64 * 256 + 4 * l);
    float4 wd1 = *(const float4*)(eW1 + 64 * 256 + 128 + 4 * l);
    float4 e20 = *(const float4*)(eW2 + 4 * l);
    float4 e21 = *(const float4*)(eW2 + 128 + 4 * l);

    // scores
    {
        const float4* hkp = (const float4*)(gHkB + (size_t)jbase * 256);
#pragma unroll
        for (int g = 0; g < 2; ++g) {
            int j0 = w * 16 + g * 8;
            float acc[8];
#pragma unroll
            for (int k = 0; k < 8; ++k) {
                int j = j0 + k;
                float4 hk0 = hkp[(size_t)j * 64 + l];
                float4 hk1 = hkp[(size_t)j * 64 + 32 + l];
                float dij = dt[j];
                acc[k] = term8(hq0, hq1, hk0, hk1, dij, wd0, wd1, e20, e21);
            }
            bfly8(acc, l);
            if (l < 8) sc[j0 + irev3(l)] = acc[0];
        }
    }
    __syncthreads();

    // local max over 128
    float m = (t < 128) ? sc[t] : -1e30f;
    m = rmax32(m);
    if (l == 0) redv[w] = m;
    __syncthreads();
    m = redv[0];
#pragma unroll
    for (int ww = 1; ww < 8; ++ww) m = fmaxf(m, redv[ww]);
    __syncthreads();

    // exp + local sum + store e
    float e = 0.0f;
    if (t < 128) {
        e = __expf(sc[t] - m);
        sc[t] = e;
        gE[row * 512 + c * 128 + t] = e;
    }
    float s = red32(e);
    if (l == 0) redv[w] = s;
    __syncthreads();
    s = 0.0f;
#pragma unroll
    for (int ww = 0; ww < 8; ++ww) s += redv[ww];

    // partial agg over the 128-chunk
    float a = 0.0f;
    for (int j = w; j < 128; j += 8) a = fmaf(sc[j], gYVB[(jbase + j) * 32 + l], a);
    part[t] = a;
    __syncthreads();
    if (t < 32) {
        float ss = 0.0f;
#pragma unroll
        for (int ww = 0; ww < 8; ++ww) ss += part[ww * 32 + t];
        gPA[(row * 4 + c) * 32 + t] = ss;
    }
    if (t == 0) { gM4[row * 4 + c] = m; gS4[row * 4 + c] = s; }

    // ---- fused combine: last block per row does old-B2 work ----
    __threadfence();
    __syncthreads();
    if (t == 0) {
        int old = atomicAdd(&gCnt[cntBase + row], 1);
        isLast = (old == 3) ? 1 : 0;
    }
    __syncthreads();
    if (!isLast) return;
    __threadfence();

    if (t == 0) {
        float m0 = gM4[row * 4 + 0], m1 = gM4[row * 4 + 1];
        float m2 = gM4[row * 4 + 2], m3 = gM4[row * 4 + 3];
        float M = fmaxf(fmaxf(m0, m1), fmaxf(m2, m3));
        float f0 = __expf(m0 - M), f1 = __expf(m1 - M);
        float f2 = __expf(m2 - M), f3 = __expf(m3 - M);
        float Z = gS4[row * 4 + 0] * f0 + gS4[row * 4 + 1] * f1
                + gS4[row * 4 + 2] * f2 + gS4[row * 4 + 3] * f3;
        float iZ = 1.0f / Z;
        fac[0] = f0 * iZ; fac[1] = f1 * iZ; fac[2] = f2 * iZ; fac[3] = f3 * iZ;
    }
    __syncthreads();

    if (edgeOut != nullptr) {
        for (int j = t; j < 512; j += 256)
            edgeOut[row * 512 + j] = gE[row * 512 + j] * fac[j >> 7];
    }
    if (!doMLP) return;

    if (t < 32) {
        float ss = 0.0f;
#pragma unroll
        for (int cc = 0; cc < 4; ++cc) ss = fmaf(gPA[(row * 4 + cc) * 32 + t], fac[cc], ss);
        zz[32 + t] = ss;
        zz[t] = gX[row * 32 + t];
    }
    __syncthreads();

    float acc2 = nb1[t];
#pragma unroll 8
    for (int c2 = 0; c2 < 64; ++c2) acc2 = fmaf(zz[c2], nW1[c2 * 256 + t], acc2);
    hh[t] = fmaxf(acc2, 0.0f);
    __syncthreads();
    float p = 0.0f;
#pragma unroll 8
    for (int j = w * 32; j < w * 32 + 32; ++j) p = fmaf(hh[j], nW2[j * 32 + l], p);
    part[t] = p;
    __syncthreads();
    if (t < 32) {
        float ss = nb2[t];
#pragma unroll
        for (int ww = 0; ww < 8; ++ww) ss += part[ww * 32 + t];
        float xn = zz[t] + ss;
        gX[row * 32 + t] = xn;
        // next-iter QKV for this robot row (warp 0, lanes 0-31)
        float aq = bqN[t], ak2 = bkN[t], av2 = bvN[t];
#pragma unroll
        for (int c2 = 0; c2 < 32; ++c2) {
            float xb = __shfl_sync(FULL, xn, c2);
            aq  = fmaf(xb, WqN[c2 * 32 + t], aq);
            ak2 = fmaf(xb, WkN[c2 * 32 + t], ak2);
            av2 = fmaf(xb, WvN[c2 * 32 + t], av2);
        }
        gQ[row * 32 + t] = aq; gK[row * 32 + t] = ak2; gV[row * 32 + t] = av2;
    }
}

// ---------------------------------------------------------------------------
extern "C" void kernel_launch(void* const* d_in, const int* in_sizes, int n_in,
                              void* d_out, int out_size) {
    const float* agent_pos    = (const float*)d_in[0];
    const float* frontier_pos = (const float*)d_in[1];
    const float* past_agent   = (const float*)d_in[2];
    const float* past_goal    = (const float*)d_in[3];
    const float* dis_rp       = (const float*)d_in[4];
    const float* dis_fp       = (const float*)d_in[5];
    const float* dis_rf       = (const float*)d_in[6];
    const float* ni_W1        = (const float*)d_in[7];
    const float* ni_b1        = (const float*)d_in[8];
    const float* ni_W2        = (const float*)d_in[9];
    const float* ni_b2        = (const float*)d_in[10];
    const float* Wq           = (const float*)d_in[11];
    const float* bq           = (const float*)d_in[12];
    const float* Wk           = (const float*)d_in[13];
    const float* bk           = (const float*)d_in[14];
    const float* Wv           = (const float*)d_in[15];
    const float* bv           = (const float*)d_in[16];
    const float* nW1          = (const float*)d_in[17];
    const float* nb1          = (const float*)d_in[18];
    const float* nW2          = (const float*)d_in[19];
    const float* nb2          = (const float*)d_in[20];
    const float* eW1          = (const float*)d_in[21];
    const float* eb1          = (const float*)d_in[22];
    const float* eW2          = (const float*)d_in[23];
    float* edge = (float*)d_out;

    k_init<<<776, 256>>>(agent_pos, frontier_pos, past_agent, past_goal,
                         ni_W1, ni_b1, ni_W2, ni_b2,
                         Wq, bq, Wk, bk, Wv, bv);

    for (int b3 = 0; b3 < 3; ++b3) {
        int nx = (b3 < 2) ? b3 + 1 : 2;   // next-iteration weight index
        const float* Wq_b  = Wq  + b3 * 32 * 32;
        const float* bq_b  = bq  + b3 * 32;
        const float* Wk_b  = Wk  + b3 * 32 * 32;
        const float* bk_b  = bk  + b3 * 32;
        const float* Wv_b  = Wv  + b3 * 32 * 32;
        const float* bv_b  = bv  + b3 * 32;
        const float* nW1_b = nW1 + b3 * 64 * 256;
        const float* nb1_b = nb1 + b3 * 256;
        const float* nW2_b = nW2 + b3 * 256 * 32;
        const float* nb2_b = nb2 + b3 * 32;
        const float* eW1_b = eW1 + b3 * 65 * 256;
        const float* eb1_b = eb1 + b3 * 256;
        const float* eW2_b = eW2 + b3 * 256;
        const float* WqN = Wq + nx * 32 * 32;
        const float* bqN = bq + nx * 32;
        const float* WkN = Wk + nx * 32 * 32;
        const float* bkN = bk + nx * 32;
        const float* WvN = Wv + nx * 32 * 32;
        const float* bvN = bv + nx * 32;

        k_intra<<<776, 256>>>(nW1_b, nb1_b, nW2_b, nb2_b,
                              Wk_b, bk_b, Wv_b, bv_b, eW1_b, eb1_b,
                              WqN, bqN, WkN, bkN, WvN, bvN);
        k_mainA<<<520, 256>>>(dis_rp, dis_fp,
                              Wq_b, bq_b, Wk_b, bk_b, Wv_b, bv_b,
                              eW1_b, eb1_b, eW2_b,
                              nW1_b, nb1_b, nW2_b, nb2_b,
                              WqN, bqN, WkN, bkN, WvN, bvN);
        float* eo = (b3 == 2) ? edge : nullptr;
        int doMLP = (b3 == 2) ? 0 : 1;
        k_mainB1<<<256, 256>>>(dis_rf, Wq_b, bq_b, eW1_b, eW2_b,
                               nW1_b, nb1_b, nW2_b, nb2_b,
                               WqN, bqN, WkN, bkN, WvN, bvN,
                               eo, doMLP, b3 * 64);
    }
}

// round 11
// speedup vs baseline: 1.5896x; 1.5896x over previous
#include <cuda_runtime.h>

#define BB 8
#define AA 8
#define FF 512
#define HH 128
#define D  32
#define HID 256

// Row layout of fused node buffer X:
#define OFF_R  0
#define OFF_F  64
#define OFF_RH 4160
#define OFF_FH 5184
#define R_TOT  6208

#define FULL 0xffffffffu

// Static device scratch
__device__ __align__(16) float gX[R_TOT * D];
__device__ __align__(16) float gQ[R_TOT * D];
__device__ __align__(16) float gK[R_TOT * D];
__device__ __align__(16) float gV[R_TOT * D];
__device__ __align__(16) float gHk[2048 * HID];    // phase A y-side hidden (+eb1): rh [0,1024), fh [1024,2048)
__device__ __align__(16) float gYV[2048 * D];      // phase A y values
__device__ __align__(16) float gHkB[4096 * HID];   // phase B y-side (frontier)
__device__ __align__(16) float gYVB[4096 * D];
// phase-B split-softmax scratch (8 chunks of 64 j)
__device__ __align__(16) float gE[64 * 512];
__device__ float gM8[64 * 8];
__device__ float gS8[64 * 8];
__device__ __align__(16) float gPA[64 * 8 * 32];

__device__ __forceinline__ float red32(float v) {
#pragma unroll
    for (int o = 16; o; o >>= 1) v += __shfl_xor_sync(FULL, v, o);
    return v;
}
__device__ __forceinline__ float rmax32(float v) {
#pragma unroll
    for (int o = 16; o; o >>= 1) v = fmaxf(v, __shfl_xor_sync(FULL, v, o));
    return v;
}
__device__ __forceinline__ float red8(float v) {
    v += __shfl_xor_sync(FULL, v, 1);
    v += __shfl_xor_sync(FULL, v, 2);
    v += __shfl_xor_sync(FULL, v, 4);
    return v;
}

// Butterfly-reduce 8 per-lane accumulators across all 32 lanes (9 shuffles).
// Afterwards lane l (l<8) holds total for index irev(l) = ((l&1)<<2)|(l&2)|((l>>2)&1).
__device__ __forceinline__ void bfly8(float (&a)[8], int l) {
    {
        bool hi = (l & 1);
#pragma unroll
        for (int k = 0; k < 4; ++k) {
            float send = hi ? a[k] : a[k + 4];
            float recv = __shfl_xor_sync(FULL, send, 1);
            a[k] = (hi ? a[k + 4] : a[k]) + recv;
        }
    }
    {
        bool hi = (l & 2);
#pragma unroll
        for (int k = 0; k < 2; ++k) {
            float send = hi ? a[k] : a[k + 2];
            float recv = __shfl_xor_sync(FULL, send, 2);
            a[k] = (hi ? a[k + 2] : a[k]) + recv;
        }
    }
    {
        bool hi = (l & 4);
        float send = hi ? a[0] : a[1];
        float recv = __shfl_xor_sync(FULL, send, 4);
        a[0] = (hi ? a[1] : a[0]) + recv;
    }
    a[0] += __shfl_xor_sync(FULL, a[0], 8);
    a[0] += __shfl_xor_sync(FULL, a[0], 16);
}
__device__ __forceinline__ int irev3(int l) {
    return ((l & 1) << 2) | (l & 2) | ((l >> 2) & 1);
}

// 8-term edge-MLP partial for one j over this lane's 8 d's
__device__ __forceinline__ float term8(const float4& hq0, const float4& hq1,
                                       const float4& a0, const float4& a1, float dij,
                                       const float4& wd0, const float4& wd1,
                                       const float4& e20, const float4& e21) {
    float acc;
    acc = fmaxf(fmaf(dij, wd0.x, hq0.x + a0.x), 0.f) * e20.x;
    acc = fmaf(fmaxf(fmaf(dij, wd0.y, hq0.y + a0.y), 0.f), e20.y, acc);
    acc = fmaf(fmaxf(fmaf(dij, wd0.z, hq0.z + a0.z), 0.f), e20.z, acc);
    acc = fmaf(fmaxf(fmaf(dij, wd0.w, hq0.w + a0.w), 0.f), e20.w, acc);
    acc = fmaf(fmaxf(fmaf(dij, wd1.x, hq1.x + a1.x), 0.f), e21.x, acc);
    acc = fmaf(fmaxf(fmaf(dij, wd1.y, hq1.y + a1.y), 0.f), e21.y, acc);
    acc = fmaf(fmaxf(fmaf(dij, wd1.z, hq1.z + a1.z), 0.f), e21.z, acc);
    acc = fmaf(fmaxf(fmaf(dij, wd1.w, hq1.w + a1.w), 0.f), e21.w, acc);
    return acc;
}

// ---------------------------------------------------------------------------
// Node-init MLP, warp-per-row (8 rows per block)
// ---------------------------------------------------------------------------
__global__ void __launch_bounds__(256) k_init(
    const float* __restrict__ ap, const float* __restrict__ fp,
    const float* __restrict__ pa, const float* __restrict__ pg,
    const float* __restrict__ W1, const float* __restrict__ b1,
    const float* __restrict__ W2, const float* __restrict__ b2) {
    __shared__ float hw[8][256];
    int w = threadIdx.x >> 5, l = threadIdx.x & 31;
    int r = blockIdx.x * 8 + w;
    const float* src;
    if (r < OFF_F)        src = ap + r * 3;
    else if (r < OFF_RH)  src = fp + (r - OFF_F) * 3;
    else if (r < OFF_FH)  src = pa + (r - OFF_RH) * 3;
    else                  src = pg + (r - OFF_FH) * 3;
    float x0 = src[0], x1 = src[1], x2 = src[2];
#pragma unroll
    for (int u = 0; u < 8; ++u) {
        int d = u * 32 + l;
        float h = fmaf(x0, W1[d], fmaf(x1, W1[256 + d], fmaf(x2, W1[512 + d], b1[d])));
        hw[w][d] = fmaxf(h, 0.0f);
    }
    __syncwarp();
    float acc = b2[l];
#pragma unroll 8
    for (int j = 0; j < 256; ++j) acc = fmaf(hw[w][j], W2[j * 32 + l], acc);
    gX[r * 32 + l] = acc;
}

// ---------------------------------------------------------------------------
// QKV projections, warp-per-row
// ---------------------------------------------------------------------------
__global__ void __launch_bounds__(256) k_qkv(
    const float* __restrict__ Wq, const float* __restrict__ bq,
    const float* __restrict__ Wk, const float* __restrict__ bk,
    const float* __restrict__ Wv, const float* __restrict__ bv) {
    int w = threadIdx.x >> 5, l = threadIdx.x & 31;
    int r = blockIdx.x * 8 + w;
    float x = gX[r * 32 + l];
    float aq = bq[l], ak = bk[l], av = bv[l];
#pragma unroll
    for (int c = 0; c < 32; ++c) {
        float xb = __shfl_sync(FULL, x, c);
        aq = fmaf(xb, Wq[c * 32 + l], aq);
        ak = fmaf(xb, Wk[c * 32 + l], ak);
        av = fmaf(xb, Wv[c * 32 + l], av);
    }
    gQ[r * 32 + l] = aq; gK[r * 32 + l] = ak; gV[r * 32 + l] = av;
}

// ---------------------------------------------------------------------------
// Intra attention, TI=8 rows per block, + fused y-side prep for rh/fh rows
// blocks: [0,8) robot  [8,520) frontier  [520,648) rh  [648,776) fh
// ---------------------------------------------------------------------------
__global__ void __launch_bounds__(256) k_intra(
    const float* __restrict__ nW1, const float* __restrict__ nb1,
    const float* __restrict__ nW2, const float* __restrict__ nb2,
    const float* __restrict__ Wk, const float* __restrict__ bk,
    const float* __restrict__ Wv, const float* __restrict__ bv,
    const float* __restrict__ eW1, const float* __restrict__ eb1) {
    __shared__ __align__(16) float qs[8][32];
    __shared__ float sc[8][512];
    __shared__ float partA[8][8][32];
    __shared__ __align__(16) float xa[64][8];
    __shared__ float hh[8][256];
    __shared__ float inv[8];

    int t = threadIdx.x, w = t >> 5, l = t & 31;
    int blk = blockIdx.x;
    int base, N, r0;
    if (blk < 8)        { base = blk * 8; N = 8; r0 = base; }
    else if (blk < 520) { int f = blk - 8;   int b = f >> 6, tl = f & 63; base = OFF_F  + b * 512; N = 512; r0 = base + tl * 8; }
    else if (blk < 648) { int g = blk - 520; int b = g >> 4, tl = g & 15; base = OFF_RH + b * 128; N = 128; r0 = base + tl * 8; }
    else                { int g = blk - 648; int b = g >> 4, tl = g & 15; base = OFF_FH + b * 128; N = 128; r0 = base + tl * 8; }

    qs[w][l] = gQ[(r0 + w) * 32 + l];
    __syncthreads();

    // scores: subwarp-8 groups, 4 j per warp in flight
    int sl = l & 7, slot = w * 4 + (l >> 3);
    for (int jj = slot; jj < N; jj += 32) {
        float4 k4 = *(const float4*)(gK + (base + jj) * 32 + sl * 4);
#pragma unroll
        for (int i = 0; i < 8; ++i) {
            float4 q4 = *(const float4*)&qs[i][sl * 4];
            float acc = q4.x * k4.x + q4.y * k4.y + q4.z * k4.z + q4.w * k4.w;
            acc = red8(acc);
            if (sl == 0) sc[i][jj] = acc;
        }
    }
    __syncthreads();

    // softmax: warp-per-i
    {
        int i = w;
        float m = -1e30f;
        for (int j = l; j < N; j += 32) m = fmaxf(m, sc[i][j]);
        m = rmax32(m);
        float s = 0.0f;
        for (int j = l; j < N; j += 32) { float e = __expf(sc[i][j] - m); sc[i][j] = e; s += e; }
        s = red32(s);
        if (l == 0) inv[i] = 1.0f / s;
    }
    __syncthreads();

    // agg: warps split j, 8 accumulators
    {
        float ac[8];
#pragma unroll
        for (int i = 0; i < 8; ++i) ac[i] = 0.0f;
        for (int j = w; j < N; j += 8) {
            float v = gV[(base + j) * 32 + l];
#pragma unroll
            for (int i = 0; i < 8; ++i) ac[i] = fmaf(sc[i][j], v, ac[i]);
        }
#pragma unroll
        for (int i = 0; i < 8; ++i) partA[w][i][l] = ac[i];
    }
    __syncthreads();
    {
        int i = w;
        float s = 0.0f;
#pragma unroll
        for (int ww = 0; ww < 8; ++ww) s += partA[ww][i][l];
        xa[32 + l][i] = s * inv[i];
        xa[l][i] = gX[(r0 + i) * 32 + l];
    }
    __syncthreads();

    // node MLP stage1
    {
        float h8[8];
        float bb = nb1[t];
#pragma unroll
        for (int i = 0; i < 8; ++i) h8[i] = bb;
#pragma unroll 4
        for (int c = 0; c < 64; ++c) {
            float w1 = nW1[c * 256 + t];
            float4 a0 = *(const float4*)&xa[c][0];
            float4 a1 = *(const float4*)&xa[c][4];
            h8[0] = fmaf(a0.x, w1, h8[0]); h8[1] = fmaf(a0.y, w1, h8[1]);
            h8[2] = fmaf(a0.z, w1, h8[2]); h8[3] = fmaf(a0.w, w1, h8[3]);
            h8[4] = fmaf(a1.x, w1, h8[4]); h8[5] = fmaf(a1.y, w1, h8[5]);
            h8[6] = fmaf(a1.z, w1, h8[6]); h8[7] = fmaf(a1.w, w1, h8[7]);
        }
#pragma unroll
        for (int i = 0; i < 8; ++i) hh[i][t] = fmaxf(h8[i], 0.0f);
    }
    __syncthreads();

    // stage2: warp-per-i output + residual + fused y-prep
    {
        int i = w;
        float acc = nb2[l];
#pragma unroll 8
        for (int j = 0; j < 256; ++j) acc = fmaf(hh[i][j], nW2[j * 32 + l], acc);
        float xn = xa[l][i] + acc;
        int r = r0 + i;
        gX[r * 32 + l] = xn;
        if (r >= OFF_RH) {  // rh/fh rows: emit hk, yv for phase A
            int hr = r - OFF_RH;
            float yk = bk[l], yv = bv[l];
#pragma unroll
            for (int c = 0; c < 32; ++c) {
                float xb = __shfl_sync(FULL, xn, c);
                yk = fmaf(xb, Wk[c * 32 + l], yk);
                yv = fmaf(xb, Wv[c * 32 + l], yv);
            }
            gYV[hr * 32 + l] = yv;
            float hk[8];
#pragma unroll
            for (int u = 0; u < 8; ++u) hk[u] = eb1[u * 32 + l];
#pragma unroll
            for (int c = 0; c < 32; ++c) {
                float ykb = __shfl_sync(FULL, yk, c);
                const float* e1 = eW1 + (32 + c) * 256;
#pragma unroll
                for (int u = 0; u < 8; ++u) hk[u] = fmaf(ykb, e1[u * 32 + l], hk[u]);
            }
#pragma unroll
            for (int u = 0; u < 8; ++u) gHk[hr * 256 + u * 32 + l] = hk[u];
        }
    }
}

// ---------------------------------------------------------------------------
// Inter phase A: j partitioned across warps, butterfly 8-i reduction,
// software-pipelined hk loads (j+1 prefetched during j's compute).
// blocks: [0,8) robot-vs-rh  [8,520) frontier-vs-fh
// ---------------------------------------------------------------------------
__global__ void __launch_bounds__(256, 2) k_mainA(
    const float* __restrict__ disRP, const float* __restrict__ disFP,
    const float* __restrict__ Wq, const float* __restrict__ bq,
    const float* __restrict__ Wk, const float* __restrict__ bk,
    const float* __restrict__ Wv, const float* __restrict__ bv,
    const float* __restrict__ eW1, const float* __restrict__ eb1,
    const float* __restrict__ eW2,
    const float* __restrict__ nW1, const float* __restrict__ nb1,
    const float* __restrict__ nW2, const float* __restrict__ nb2) {
    __shared__ __align__(16) float hqs[8][256];
    __shared__ float dt[1024];
    __shared__ float sc[8][128];
    __shared__ float partA[8][8][32];
    __shared__ __align__(16) float xa[64][8];
    __shared__ float hh[8][256];
    __shared__ float inv[8];

    int t = threadIdx.x, w = t >> 5, l = t & 31;
    int blk = blockIdx.x;
    int xrow0, hkbase, isF;
    const float* disrow;
    if (blk < 8) { xrow0 = blk * 8; hkbase = blk * 128; isF = 0; disrow = disRP + blk * 8 * 128; }
    else {
        int f = blk - 8; int b = f >> 6, tl = f & 63;
        xrow0 = OFF_F + b * 512 + tl * 8; hkbase = 1024 + b * 128; isF = 1;
        disrow = disFP + (b * 512 + tl * 8) * 128;
    }

    // x-side: xq = X@Wq+bq ; hq = xq@eW1[0:32]  (warp-per-i, layout d=u*32+l)
    {
        float x = gX[(xrow0 + w) * 32 + l];
        float xq = bq[l];
#pragma unroll
        for (int c = 0; c < 32; ++c) xq = fmaf(__shfl_sync(FULL, x, c), Wq[c * 32 + l], xq);
        float hq[8];
#pragma unroll
        for (int u = 0; u < 8; ++u) hq[u] = 0.0f;
#pragma unroll
        for (int c = 0; c < 32; ++c) {
            float xqb = __shfl_sync(FULL, xq, c);
            const float* e1 = eW1 + c * 256;
#pragma unroll
            for (int u = 0; u < 8; ++u) hq[u] = fmaf(xqb, e1[u * 32 + l], hq[u]);
        }
#pragma unroll
        for (int u = 0; u < 8; ++u) hqs[w][u * 32 + l] = hq[u];
    }
    for (int idx = t; idx < 1024; idx += 256) dt[idx] = disrow[idx];
    __syncthreads();

    // lane-resident weight slices: d = 4l..4l+3 and 128+4l..128+4l+3
    float4 wd0 = *(const float4*)(eW1 + 64 * 256 + 4 * l);
    float4 wd1 = *(const float4*)(eW1 + 64 * 256 + 128 + 4 * l);
    float4 e20 = *(const float4*)(eW2 + 4 * l);
    float4 e21 = *(const float4*)(eW2 + 128 + 4 * l);

    // scores: warp w handles j in [16w, 16w+16); hk loads software-pipelined
    {
        const float4* hkp = (const float4*)(gHk + (size_t)hkbase * 256);
        int j0 = w * 16;
        float4 hk0 = hkp[(size_t)j0 * 64 + l];
        float4 hk1 = hkp[(size_t)j0 * 64 + 32 + l];
        for (int jj = 0; jj < 16; ++jj) {
            int j = j0 + jj;
            float4 nk0, nk1;
            if (jj < 15) {
                nk0 = hkp[(size_t)(j + 1) * 64 + l];
                nk1 = hkp[(size_t)(j + 1) * 64 + 32 + l];
            }
            float dj[8];
#pragma unroll
            for (int i = 0; i < 8; ++i) dj[i] = dt[i * 128 + j];
            float acc[8];
#pragma unroll
            for (int i = 0; i < 8; ++i) {
                float4 hq0 = *(const float4*)&hqs[i][4 * l];
                float4 hq1 = *(const float4*)&hqs[i][128 + 4 * l];
                acc[i] = term8(hq0, hq1, hk0, hk1, dj[i], wd0, wd1, e20, e21);
            }
            bfly8(acc, l);
            if (l < 8) sc[irev3(l)][j] = acc[0];
            hk0 = nk0; hk1 = nk1;
        }
    }
    __syncthreads();

    // softmax warp-per-i
    {
        int i = w;
        float m = -1e30f;
#pragma unroll
        for (int k = 0; k < 4; ++k) m = fmaxf(m, sc[i][l + 32 * k]);
        m = rmax32(m);
        float s = 0.0f;
#pragma unroll
        for (int k = 0; k < 4; ++k) {
            float e = __expf(sc[i][l + 32 * k] - m);
            sc[i][l + 32 * k] = e; s += e;
        }
        s = red32(s);
        if (l == 0) inv[i] = 1.0f / s;
    }
    __syncthreads();

    // agg
    {
        float ac[8];
#pragma unroll
        for (int i = 0; i < 8; ++i) ac[i] = 0.0f;
        for (int j = w; j < 128; j += 8) {
            float v = gYV[(hkbase + j) * 32 + l];
#pragma unroll
            for (int i = 0; i < 8; ++i) ac[i] = fmaf(sc[i][j], v, ac[i]);
        }
#pragma unroll
        for (int i = 0; i < 8; ++i) partA[w][i][l] = ac[i];
    }
    __syncthreads();
    {
        int i = w;
        float s = 0.0f;
#pragma unroll
        for (int ww = 0; ww < 8; ++ww) s += partA[ww][i][l];
        xa[32 + l][i] = s * inv[i];
        xa[l][i] = gX[(xrow0 + i) * 32 + l];
    }
    __syncthreads();

    // node MLP stage1
    {
        float h8[8];
        float bb = nb1[t];
#pragma unroll
        for (int i = 0; i < 8; ++i) h8[i] = bb;
#pragma unroll 4
        for (int c = 0; c < 64; ++c) {
            float w1 = nW1[c * 256 + t];
            float4 a0 = *(const float4*)&xa[c][0];
            float4 a1 = *(const float4*)&xa[c][4];
            h8[0] = fmaf(a0.x, w1, h8[0]); h8[1] = fmaf(a0.y, w1, h8[1]);
            h8[2] = fmaf(a0.z, w1, h8[2]); h8[3] = fmaf(a0.w, w1, h8[3]);
            h8[4] = fmaf(a1.x, w1, h8[4]); h8[5] = fmaf(a1.y, w1, h8[5]);
            h8[6] = fmaf(a1.z, w1, h8[6]); h8[7] = fmaf(a1.w, w1, h8[7]);
        }
#pragma unroll
        for (int i = 0; i < 8; ++i) hh[i][t] = fmaxf(h8[i], 0.0f);
    }
    __syncthreads();

    // stage2 + phase-B prep for frontier rows
    {
        int i = w;
        float acc = nb2[l];
#pragma unroll 8
        for (int j = 0; j < 256; ++j) acc = fmaf(hh[i][j], nW2[j * 32 + l], acc);
        float xn = xa[l][i] + acc;
        gX[(xrow0 + i) * 32 + l] = xn;
        if (isF) {
            int hr = xrow0 - OFF_F + i;
            float yk = bk[l], yv = bv[l];
#pragma unroll
            for (int c = 0; c < 32; ++c) {
                float xb = __shfl_sync(FULL, xn, c);
                yk = fmaf(xb, Wk[c * 32 + l], yk);
                yv = fmaf(xb, Wv[c * 32 + l], yv);
            }
            gYVB[hr * 32 + l] = yv;
            float hk[8];
#pragma unroll
            for (int u = 0; u < 8; ++u) hk[u] = eb1[u * 32 + l];
#pragma unroll
            for (int c = 0; c < 32; ++c) {
                float ykb = __shfl_sync(FULL, yk, c);
                const float* e1 = eW1 + (32 + c) * 256;
#pragma unroll
                for (int u = 0; u < 8; ++u) hk[u] = fmaf(ykb, e1[u * 32 + l], hk[u]);
            }
#pragma unroll
            for (int u = 0; u < 8; ++u) gHkB[hr * 256 + u * 32 + l] = hk[u];
        }
    }
}

// ---------------------------------------------------------------------------
// Phase B part 1: split softmax. grid = 64 rows x 8 chunks of 64 j.
// Each warp does exactly one butterfly group of 8 j.
// ---------------------------------------------------------------------------
__global__ void __launch_bounds__(256) k_mainB1(
    const float* __restrict__ disRF,
    const float* __restrict__ Wq, const float* __restrict__ bq,
    const float* __restrict__ eW1, const float* __restrict__ eW2) {
    __shared__ __align__(16) float hqs[256];
    __shared__ float dt[64];
    __shared__ float sc[64];
    __shared__ float redv[8];
    __shared__ float part[256];

    int t = threadIdx.x, w = t >> 5, l = t & 31;
    int row = blockIdx.x >> 3, c = blockIdx.x & 7;
    int b = row >> 3;
    int jbase = b * 512 + c * 64;   // row base into gHkB / gYVB

    // x-side hq (warp w computes hq chunk w*32)
    {
        float x = gX[row * 32 + l];
        float xq = bq[l];
#pragma unroll
        for (int c2 = 0; c2 < 32; ++c2) xq = fmaf(__shfl_sync(FULL, x, c2), Wq[c2 * 32 + l], xq);
        float h = 0.0f;
#pragma unroll
        for (int c2 = 0; c2 < 32; ++c2)
            h = fmaf(__shfl_sync(FULL, xq, c2), eW1[c2 * 256 + w * 32 + l], h);
        hqs[w * 32 + l] = h;
    }
    if (t < 64) dt[t] = disRF[row * 512 + c * 64 + t];
    __syncthreads();

    float4 hq0 = *(const float4*)&hqs[4 * l];
    float4 hq1 = *(const float4*)&hqs[128 + 4 * l];
    float4 wd0 = *(const float4*)(eW1 + 64 * 256 + 4 * l);
    float4 wd1 = *(const float4*)(eW1 + 64 * 256 + 128 + 4 * l);
    float4 e20 = *(const float4*)(eW2 + 4 * l);
    float4 e21 = *(const float4*)(eW2 + 128 + 4 * l);

    // scores: warp w handles j in [w*8, w*8+8) — one butterfly group
    {
        const float4* hkp = (const float4*)(gHkB + (size_t)jbase * 256);
        int j0 = w * 8;
        float acc[8];
#pragma unroll
        for (int k = 0; k < 8; ++k) {
            int j = j0 + k;
            float4 hk0 = hkp[(size_t)j * 64 + l];
            float4 hk1 = hkp[(size_t)j * 64 + 32 + l];
            float dij = dt[j];
            acc[k] = term8(hq0, hq1, hk0, hk1, dij, wd0, wd1, e20, e21);
        }
        bfly8(acc, l);
        if (l < 8) sc[j0 + irev3(l)] = acc[0];
    }
    __syncthreads();

    // local max over 64
    float m = (t < 64) ? sc[t] : -1e30f;
    m = rmax32(m);
    if (l == 0) redv[w] = m;
    __syncthreads();
    m = redv[0];
#pragma unroll
    for (int ww = 1; ww < 8; ++ww) m = fmaxf(m, redv[ww]);
    __syncthreads();

    // exp + local sum + store e
    float e = 0.0f;
    if (t < 64) {
        e = __expf(sc[t] - m);
        sc[t] = e;
        gE[row * 512 + c * 64 + t] = e;
    }
    float s = red32(e);
    if (l == 0) redv[w] = s;
    __syncthreads();
    s = 0.0f;
#pragma unroll
    for (int ww = 0; ww < 8; ++ww) s += redv[ww];

    // partial agg over the 64-chunk
    float a = 0.0f;
    for (int j = w; j < 64; j += 8) a = fmaf(sc[j], gYVB[(jbase + j) * 32 + l], a);
    part[t] = a;
    __syncthreads();
    if (t < 32) {
        float ss = 0.0f;
#pragma unroll
        for (int ww = 0; ww < 8; ++ww) ss += part[ww * 32 + t];
        gPA[(row * 8 + c) * 32 + t] = ss;
    }
    if (t == 0) { gM8[row * 8 + c] = m; gS8[row * 8 + c] = s; }
}

// ---------------------------------------------------------------------------
// Phase B part 2: combine 8 chunks, write edge / node-MLP. grid = 64 rows.
// ---------------------------------------------------------------------------
__global__ void __launch_bounds__(256) k_mainB2(
    const float* __restrict__ nW1, const float* __restrict__ nb1,
    const float* __restrict__ nW2, const float* __restrict__ nb2,
    float* edgeOut, int doMLP) {
    __shared__ float fac[8];
    __shared__ float zz[64];
    __shared__ float hh[256];
    __shared__ float part[256];

    int t = threadIdx.x, w = t >> 5, l = t & 31;
    int row = blockIdx.x;

    if (t < 32) {
        // lanes 0-7 hold chunk data; warp-reduce max and weighted sum
        float mv = (l < 8) ? gM8[row * 8 + l] : -1e30f;
        float sv = (l < 8) ? gS8[row * 8 + l] : 0.0f;
        float M = rmax32(mv);
        float f = (l < 8) ? __expf(mv - M) : 0.0f;
        float Z = red32(sv * f);
        if (l < 8) fac[l] = f / Z;
    }
    __syncthreads();

    if (edgeOut != nullptr) {
        for (int j = t; j < 512; j += 256)
            edgeOut[row * 512 + j] = gE[row * 512 + j] * fac[j >> 6];
    }
    if (!doMLP) return;

    if (t < 32) {
        float ss = 0.0f;
#pragma unroll
        for (int cc = 0; cc < 8; ++cc) ss = fmaf(gPA[(row * 8 + cc) * 32 + t], fac[cc], ss);
        zz[32 + t] = ss;
        zz[t] = gX[row * 32 + t];
    }
    __syncthreads();

    float acc = nb1[t];
#pragma unroll 8
    for (int c = 0; c < 64; ++c) acc = fmaf(zz[c], nW1[c * 256 + t], acc);
    hh[t] = fmaxf(acc, 0.0f);
    __syncthreads();
    float p = 0.0f;
#pragma unroll 8
    for (int j = w * 32; j < w * 32 + 32; ++j) p = fmaf(hh[j], nW2[j * 32 + l], p);
    part[t] = p;
    __syncthreads();
    if (t < 32) {
        float ss = nb2[t];
#pragma unroll
        for (int ww = 0; ww < 8; ++ww) ss += part[ww * 32 + t];
        gX[row * 32 + t] = zz[t] + ss;
    }
}

// ---------------------------------------------------------------------------
extern "C" void kernel_launch(void* const* d_in, const int* in_sizes, int n_in,
                              void* d_out, int out_size) {
    const float* agent_pos    = (const float*)d_in[0];
    const float* frontier_pos = (const float*)d_in[1];
    const float* past_agent   = (const float*)d_in[2];
    const float* past_goal    = (const float*)d_in[3];
    const float* dis_rp       = (const float*)d_in[4];
    const float* dis_fp       = (const float*)d_in[5];
    const float* dis_rf       = (const float*)d_in[6];
    const float* ni_W1        = (const float*)d_in[7];
    const float* ni_b1        = (const float*)d_in[8];
    const float* ni_W2        = (const float*)d_in[9];
    const float* ni_b2        = (const float*)d_in[10];
    const float* Wq           = (const float*)d_in[11];
    const float* bq           = (const float*)d_in[12];
    const float* Wk           = (const float*)d_in[13];
    const float* bk           = (const float*)d_in[14];
    const float* Wv           = (const float*)d_in[15];
    const float* bv           = (const float*)d_in[16];
    const float* nW1          = (const float*)d_in[17];
    const float* nb1          = (const float*)d_in[18];
    const float* nW2          = (const float*)d_in[19];
    const float* nb2          = (const float*)d_in[20];
    const float* eW1          = (const float*)d_in[21];
    const float* eb1          = (const float*)d_in[22];
    const float* eW2          = (const float*)d_in[23];
    float* edge = (float*)d_out;

    k_init<<<776, 256>>>(agent_pos, frontier_pos, past_agent, past_goal,
                         ni_W1, ni_b1, ni_W2, ni_b2);

    for (int b3 = 0; b3 < 3; ++b3) {
        const float* Wq_b  = Wq  + b3 * 32 * 32;
        const float* bq_b  = bq  + b3 * 32;
        const float* Wk_b  = Wk  + b3 * 32 * 32;
        const float* bk_b  = bk  + b3 * 32;
        const float* Wv_b  = Wv  + b3 * 32 * 32;
        const float* bv_b  = bv  + b3 * 32;
        const float* nW1_b = nW1 + b3 * 64 * 256;
        const float* nb1_b = nb1 + b3 * 256;
        const float* nW2_b = nW2 + b3 * 256 * 32;
        const float* nb2_b = nb2 + b3 * 32;
        const float* eW1_b = eW1 + b3 * 65 * 256;
        const float* eb1_b = eb1 + b3 * 256;
        const float* eW2_b = eW2 + b3 * 256;

        k_qkv<<<776, 256>>>(Wq_b, bq_b, Wk_b, bk_b, Wv_b, bv_b);
        k_intra<<<776, 256>>>(nW1_b, nb1_b, nW2_b, nb2_b,
                              Wk_b, bk_b, Wv_b, bv_b, eW1_b, eb1_b);
        k_mainA<<<520, 256>>>(dis_rp, dis_fp,
                              Wq_b, bq_b, Wk_b, bk_b, Wv_b, bv_b,
                              eW1_b, eb1_b, eW2_b,
                              nW1_b, nb1_b, nW2_b, nb2_b);
        k_mainB1<<<512, 256>>>(dis_rf, Wq_b, bq_b, eW1_b, eW2_b);
        float* eo = (b3 == 2) ? edge : nullptr;
        int doMLP = (b3 == 2) ? 0 : 1;
        k_mainB2<<<64, 256>>>(nW1_b, nb1_b, nW2_b, nb2_b, eo, doMLP);
    }
}

// round 12
// speedup vs baseline: 1.5980x; 1.0053x over previous
#include <cuda_runtime.h>

#define BB 8
#define AA 8
#define FF 512
#define HH 128
#define D  32
#define HID 256

// Row layout of fused node buffer X:
#define OFF_R  0
#define OFF_F  64
#define OFF_RH 4160
#define OFF_FH 5184
#define R_TOT  6208

#define FULL 0xffffffffu

// Static device scratch
__device__ __align__(16) float gX[R_TOT * D];
__device__ __align__(16) float gQ[R_TOT * D];
__device__ __align__(16) float gK[R_TOT * D];
__device__ __align__(16) float gV[R_TOT * D];
__device__ __align__(16) float gHk[2048 * HID];    // phase A y-side hidden (+eb1): rh [0,1024), fh [1024,2048)
__device__ __align__(16) float gYV[2048 * D];      // phase A y values
__device__ __align__(16) float gHkB[4096 * HID];   // phase B y-side (frontier)
__device__ __align__(16) float gYVB[4096 * D];
// phase-B split-softmax scratch (8 chunks of 64 j)
__device__ __align__(16) float gE[64 * 512];
__device__ float gM8[64 * 8];
__device__ float gS8[64 * 8];
__device__ __align__(16) float gPA[64 * 8 * 32];
__device__ int gCnt[192];   // 3 iterations x 64 rows, zeroed by k_init each replay

__device__ __forceinline__ float red32(float v) {
#pragma unroll
    for (int o = 16; o; o >>= 1) v += __shfl_xor_sync(FULL, v, o);
    return v;
}
__device__ __forceinline__ float rmax32(float v) {
#pragma unroll
    for (int o = 16; o; o >>= 1) v = fmaxf(v, __shfl_xor_sync(FULL, v, o));
    return v;
}
__device__ __forceinline__ float red8(float v) {
    v += __shfl_xor_sync(FULL, v, 1);
    v += __shfl_xor_sync(FULL, v, 2);
    v += __shfl_xor_sync(FULL, v, 4);
    return v;
}

// Butterfly-reduce 8 per-lane accumulators across all 32 lanes (9 shuffles).
// Afterwards lane l (l<8) holds total for index irev(l) = ((l&1)<<2)|(l&2)|((l>>2)&1).
__device__ __forceinline__ void bfly8(float (&a)[8], int l) {
    {
        bool hi = (l & 1);
#pragma unroll
        for (int k = 0; k < 4; ++k) {
            float send = hi ? a[k] : a[k + 4];
            float recv = __shfl_xor_sync(FULL, send, 1);
            a[k] = (hi ? a[k + 4] : a[k]) + recv;
        }
    }
    {
        bool hi = (l & 2);
#pragma unroll
        for (int k = 0; k < 2; ++k) {
            float send = hi ? a[k] : a[k + 2];
            float recv = __shfl_xor_sync(FULL, send, 2);
            a[k] = (hi ? a[k + 2] : a[k]) + recv;
        }
    }
    {
        bool hi = (l & 4);
        float send = hi ? a[0] : a[1];
        float recv = __shfl_xor_sync(FULL, send, 4);
        a[0] = (hi ? a[1] : a[0]) + recv;
    }
    a[0] += __shfl_xor_sync(FULL, a[0], 8);
    a[0] += __shfl_xor_sync(FULL, a[0], 16);
}
__device__ __forceinline__ int irev3(int l) {
    return ((l & 1) << 2) | (l & 2) | ((l >> 2) & 1);
}

// 8-term edge-MLP partial for one j over this lane's 8 d's
__device__ __forceinline__ float term8(const float4& hq0, const float4& hq1,
                                       const float4& a0, const float4& a1, float dij,
                                       const float4& wd0, const float4& wd1,
                                       const float4& e20, const float4& e21) {
    float acc;
    acc = fmaxf(fmaf(dij, wd0.x, hq0.x + a0.x), 0.f) * e20.x;
    acc = fmaf(fmaxf(fmaf(dij, wd0.y, hq0.y + a0.y), 0.f), e20.y, acc);
    acc = fmaf(fmaxf(fmaf(dij, wd0.z, hq0.z + a0.z), 0.f), e20.z, acc);
    acc = fmaf(fmaxf(fmaf(dij, wd0.w, hq0.w + a0.w), 0.f), e20.w, acc);
    acc = fmaf(fmaxf(fmaf(dij, wd1.x, hq1.x + a1.x), 0.f), e21.x, acc);
    acc = fmaf(fmaxf(fmaf(dij, wd1.y, hq1.y + a1.y), 0.f), e21.y, acc);
    acc = fmaf(fmaxf(fmaf(dij, wd1.z, hq1.z + a1.z), 0.f), e21.z, acc);
    acc = fmaf(fmaxf(fmaf(dij, wd1.w, hq1.w + a1.w), 0.f), e21.w, acc);
    return acc;
}

// ---------------------------------------------------------------------------
// Node-init MLP, warp-per-row (8 rows per block) + counter reset
// ---------------------------------------------------------------------------
__global__ void __launch_bounds__(256) k_init(
    const float* __restrict__ ap, const float* __restrict__ fp,
    const float* __restrict__ pa, const float* __restrict__ pg,
    const float* __restrict__ W1, const float* __restrict__ b1,
    const float* __restrict__ W2, const float* __restrict__ b2) {
    __shared__ float hw[8][256];
    int w = threadIdx.x >> 5, l = threadIdx.x & 31;
    if (blockIdx.x == 0 && threadIdx.x < 192) gCnt[threadIdx.x] = 0;
    int r = blockIdx.x * 8 + w;
    const float* src;
    if (r < OFF_F)        src = ap + r * 3;
    else if (r < OFF_RH)  src = fp + (r - OFF_F) * 3;
    else if (r < OFF_FH)  src = pa + (r - OFF_RH) * 3;
    else                  src = pg + (r - OFF_FH) * 3;
    float x0 = src[0], x1 = src[1], x2 = src[2];
#pragma unroll
    for (int u = 0; u < 8; ++u) {
        int d = u * 32 + l;
        float h = fmaf(x0, W1[d], fmaf(x1, W1[256 + d], fmaf(x2, W1[512 + d], b1[d])));
        hw[w][d] = fmaxf(h, 0.0f);
    }
    __syncwarp();
    float acc = b2[l];
#pragma unroll 8
    for (int j = 0; j < 256; ++j) acc = fmaf(hw[w][j], W2[j * 32 + l], acc);
    gX[r * 32 + l] = acc;
}

// ---------------------------------------------------------------------------
// QKV projections, warp-per-row
// ---------------------------------------------------------------------------
__global__ void __launch_bounds__(256) k_qkv(
    const float* __restrict__ Wq, const float* __restrict__ bq,
    const float* __restrict__ Wk, const float* __restrict__ bk,
    const float* __restrict__ Wv, const float* __restrict__ bv) {
    int w = threadIdx.x >> 5, l = threadIdx.x & 31;
    int r = blockIdx.x * 8 + w;
    float x = gX[r * 32 + l];
    float aq = bq[l], ak = bk[l], av = bv[l];
#pragma unroll
    for (int c = 0; c < 32; ++c) {
        float xb = __shfl_sync(FULL, x, c);
        aq = fmaf(xb, Wq[c * 32 + l], aq);
        ak = fmaf(xb, Wk[c * 32 + l], ak);
        av = fmaf(xb, Wv[c * 32 + l], av);
    }
    gQ[r * 32 + l] = aq; gK[r * 32 + l] = ak; gV[r * 32 + l] = av;
}

// ---------------------------------------------------------------------------
// Intra attention, TI=8 rows per block, + fused y-side prep for rh/fh rows
// blocks: [0,8) robot  [8,520) frontier  [520,648) rh  [648,776) fh
// ---------------------------------------------------------------------------
__global__ void __launch_bounds__(256) k_intra(
    const float* __restrict__ nW1, const float* __restrict__ nb1,
    const float* __restrict__ nW2, const float* __restrict__ nb2,
    const float* __restrict__ Wk, const float* __restrict__ bk,
    const float* __restrict__ Wv, const float* __restrict__ bv,
    const float* __restrict__ eW1, const float* __restrict__ eb1) {
    __shared__ __align__(16) float qs[8][32];
    __shared__ float sc[8][512];
    __shared__ float partA[8][8][32];
    __shared__ __align__(16) float xa[64][8];
    __shared__ float hh[8][256];
    __shared__ float inv[8];

    int t = threadIdx.x, w = t >> 5, l = t & 31;
    int blk = blockIdx.x;
    int base, N, r0;
    if (blk < 8)        { base = blk * 8; N = 8; r0 = base; }
    else if (blk < 520) { int f = blk - 8;   int b = f >> 6, tl = f & 63; base = OFF_F  + b * 512; N = 512; r0 = base + tl * 8; }
    else if (blk < 648) { int g = blk - 520; int b = g >> 4, tl = g & 15; base = OFF_RH + b * 128; N = 128; r0 = base + tl * 8; }
    else                { int g = blk - 648; int b = g >> 4, tl = g & 15; base = OFF_FH + b * 128; N = 128; r0 = base + tl * 8; }

    qs[w][l] = gQ[(r0 + w) * 32 + l];
    __syncthreads();

    // scores: subwarp-8 groups, 4 j per warp in flight
    int sl = l & 7, slot = w * 4 + (l >> 3);
    for (int jj = slot; jj < N; jj += 32) {
        float4 k4 = *(const float4*)(gK + (base + jj) * 32 + sl * 4);
#pragma unroll
        for (int i = 0; i < 8; ++i) {
            float4 q4 = *(const float4*)&qs[i][sl * 4];
            float acc = q4.x * k4.x + q4.y * k4.y + q4.z * k4.z + q4.w * k4.w;
            acc = red8(acc);
            if (sl == 0) sc[i][jj] = acc;
        }
    }
    __syncthreads();

    // softmax: warp-per-i
    {
        int i = w;
        float m = -1e30f;
        for (int j = l; j < N; j += 32) m = fmaxf(m, sc[i][j]);
        m = rmax32(m);
        float s = 0.0f;
        for (int j = l; j < N; j += 32) { float e = __expf(sc[i][j] - m); sc[i][j] = e; s += e; }
        s = red32(s);
        if (l == 0) inv[i] = 1.0f / s;
    }
    __syncthreads();

    // agg: warps split j, 8 accumulators
    {
        float ac[8];
#pragma unroll
        for (int i = 0; i < 8; ++i) ac[i] = 0.0f;
        for (int j = w; j < N; j += 8) {
            float v = gV[(base + j) * 32 + l];
#pragma unroll
            for (int i = 0; i < 8; ++i) ac[i] = fmaf(sc[i][j], v, ac[i]);
        }
#pragma unroll
        for (int i = 0; i < 8; ++i) partA[w][i][l] = ac[i];
    }
    __syncthreads();
    {
        int i = w;
        float s = 0.0f;
#pragma unroll
        for (int ww = 0; ww < 8; ++ww) s += partA[ww][i][l];
        xa[32 + l][i] = s * inv[i];
        xa[l][i] = gX[(r0 + i) * 32 + l];
    }
    __syncthreads();

    // node MLP stage1
    {
        float h8[8];
        float bb = nb1[t];
#pragma unroll
        for (int i = 0; i < 8; ++i) h8[i] = bb;
#pragma unroll 4
        for (int c = 0; c < 64; ++c) {
            float w1 = nW1[c * 256 + t];
            float4 a0 = *(const float4*)&xa[c][0];
            float4 a1 = *(const float4*)&xa[c][4];
            h8[0] = fmaf(a0.x, w1, h8[0]); h8[1] = fmaf(a0.y, w1, h8[1]);
            h8[2] = fmaf(a0.z, w1, h8[2]); h8[3] = fmaf(a0.w, w1, h8[3]);
            h8[4] = fmaf(a1.x, w1, h8[4]); h8[5] = fmaf(a1.y, w1, h8[5]);
            h8[6] = fmaf(a1.z, w1, h8[6]); h8[7] = fmaf(a1.w, w1, h8[7]);
        }
#pragma unroll
        for (int i = 0; i < 8; ++i) hh[i][t] = fmaxf(h8[i], 0.0f);
    }
    __syncthreads();

    // stage2: warp-per-i output + residual + fused y-prep
    {
        int i = w;
        float acc = nb2[l];
#pragma unroll 8
        for (int j = 0; j < 256; ++j) acc = fmaf(hh[i][j], nW2[j * 32 + l], acc);
        float xn = xa[l][i] + acc;
        int r = r0 + i;
        gX[r * 32 + l] = xn;
        if (r >= OFF_RH) {  // rh/fh rows: emit hk, yv for phase A
            int hr = r - OFF_RH;
            float yk = bk[l], yv = bv[l];
#pragma unroll
            for (int c = 0; c < 32; ++c) {
                float xb = __shfl_sync(FULL, xn, c);
                yk = fmaf(xb, Wk[c * 32 + l], yk);
                yv = fmaf(xb, Wv[c * 32 + l], yv);
            }
            gYV[hr * 32 + l] = yv;
            float hk[8];
#pragma unroll
            for (int u = 0; u < 8; ++u) hk[u] = eb1[u * 32 + l];
#pragma unroll
            for (int c = 0; c < 32; ++c) {
                float ykb = __shfl_sync(FULL, yk, c);
                const float* e1 = eW1 + (32 + c) * 256;
#pragma unroll
                for (int u = 0; u < 8; ++u) hk[u] = fmaf(ykb, e1[u * 32 + l], hk[u]);
            }
#pragma unroll
            for (int u = 0; u < 8; ++u) gHk[hr * 256 + u * 32 + l] = hk[u];
        }
    }
}

// ---------------------------------------------------------------------------
// Inter phase A: j partitioned across warps, butterfly 8-i reduction,
// software-pipelined hk loads (j+1 prefetched during j's compute).
// blocks: [0,8) robot-vs-rh  [8,520) frontier-vs-fh
// ---------------------------------------------------------------------------
__global__ void __launch_bounds__(256, 2) k_mainA(
    const float* __restrict__ disRP, const float* __restrict__ disFP,
    const float* __restrict__ Wq, const float* __restrict__ bq,
    const float* __restrict__ Wk, const float* __restrict__ bk,
    const float* __restrict__ Wv, const float* __restrict__ bv,
    const float* __restrict__ eW1, const float* __restrict__ eb1,
    const float* __restrict__ eW2,
    const float* __restrict__ nW1, const float* __restrict__ nb1,
    const float* __restrict__ nW2, const float* __restrict__ nb2) {
    __shared__ __align__(16) float hqs[8][256];
    __shared__ float dt[1024];
    __shared__ float sc[8][128];
    __shared__ float partA[8][8][32];
    __shared__ __align__(16) float xa[64][8];
    __shared__ float hh[8][256];
    __shared__ float inv[8];

    int t = threadIdx.x, w = t >> 5, l = t & 31;
    int blk = blockIdx.x;
    int xrow0, hkbase, isF;
    const float* disrow;
    if (blk < 8) { xrow0 = blk * 8; hkbase = blk * 128; isF = 0; disrow = disRP + blk * 8 * 128; }
    else {
        int f = blk - 8; int b = f >> 6, tl = f & 63;
        xrow0 = OFF_F + b * 512 + tl * 8; hkbase = 1024 + b * 128; isF = 1;
        disrow = disFP + (b * 512 + tl * 8) * 128;
    }

    // x-side: xq = X@Wq+bq ; hq = xq@eW1[0:32]  (warp-per-i, layout d=u*32+l)
    {
        float x = gX[(xrow0 + w) * 32 + l];
        float xq = bq[l];
#pragma unroll
        for (int c = 0; c < 32; ++c) xq = fmaf(__shfl_sync(FULL, x, c), Wq[c * 32 + l], xq);
        float hq[8];
#pragma unroll
        for (int u = 0; u < 8; ++u) hq[u] = 0.0f;
#pragma unroll
        for (int c = 0; c < 32; ++c) {
            float xqb = __shfl_sync(FULL, xq, c);
            const float* e1 = eW1 + c * 256;
#pragma unroll
            for (int u = 0; u < 8; ++u) hq[u] = fmaf(xqb, e1[u * 32 + l], hq[u]);
        }
#pragma unroll
        for (int u = 0; u < 8; ++u) hqs[w][u * 32 + l] = hq[u];
    }
    for (int idx = t; idx < 1024; idx += 256) dt[idx] = disrow[idx];
    __syncthreads();

    // lane-resident weight slices: d = 4l..4l+3 and 128+4l..128+4l+3
    float4 wd0 = *(const float4*)(eW1 + 64 * 256 + 4 * l);
    float4 wd1 = *(const float4*)(eW1 + 64 * 256 + 128 + 4 * l);
    float4 e20 = *(const float4*)(eW2 + 4 * l);
    float4 e21 = *(const float4*)(eW2 + 128 + 4 * l);

    // scores: warp w handles j in [16w, 16w+16); hk loads software-pipelined
    {
        const float4* hkp = (const float4*)(gHk + (size_t)hkbase * 256);
        int j0 = w * 16;
        float4 hk0 = hkp[(size_t)j0 * 64 + l];
        float4 hk1 = hkp[(size_t)j0 * 64 + 32 + l];
        for (int jj = 0; jj < 16; ++jj) {
            int j = j0 + jj;
            float4 nk0, nk1;
            if (jj < 15) {
                nk0 = hkp[(size_t)(j + 1) * 64 + l];
                nk1 = hkp[(size_t)(j + 1) * 64 + 32 + l];
            }
            float dj[8];
#pragma unroll
            for (int i = 0; i < 8; ++i) dj[i] = dt[i * 128 + j];
            float acc[8];
#pragma unroll
            for (int i = 0; i < 8; ++i) {
                float4 hq0 = *(const float4*)&hqs[i][4 * l];
                float4 hq1 = *(const float4*)&hqs[i][128 + 4 * l];
                acc[i] = term8(hq0, hq1, hk0, hk1, dj[i], wd0, wd1, e20, e21);
            }
            bfly8(acc, l);
            if (l < 8) sc[irev3(l)][j] = acc[0];
            hk0 = nk0; hk1 = nk1;
        }
    }
    __syncthreads();

    // softmax warp-per-i
    {
        int i = w;
        float m = -1e30f;
#pragma unroll
        for (int k = 0; k < 4; ++k) m = fmaxf(m, sc[i][l + 32 * k]);
        m = rmax32(m);
        float s = 0.0f;
#pragma unroll
        for (int k = 0; k < 4; ++k) {
            float e = __expf(sc[i][l + 32 * k] - m);
            sc[i][l + 32 * k] = e; s += e;
        }
        s = red32(s);
        if (l == 0) inv[i] = 1.0f / s;
    }
    __syncthreads();

    // agg
    {
        float ac[8];
#pragma unroll
        for (int i = 0; i < 8; ++i) ac[i] = 0.0f;
        for (int j = w; j < 128; j += 8) {
            float v = gYV[(hkbase + j) * 32 + l];
#pragma unroll
            for (int i = 0; i < 8; ++i) ac[i] = fmaf(sc[i][j], v, ac[i]);
        }
#pragma unroll
        for (int i = 0; i < 8; ++i) partA[w][i][l] = ac[i];
    }
    __syncthreads();
    {
        int i = w;
        float s = 0.0f;
#pragma unroll
        for (int ww = 0; ww < 8; ++ww) s += partA[ww][i][l];
        xa[32 + l][i] = s * inv[i];
        xa[l][i] = gX[(xrow0 + i) * 32 + l];
    }
    __syncthreads();

    // node MLP stage1
    {
        float h8[8];
        float bb = nb1[t];
#pragma unroll
        for (int i = 0; i < 8; ++i) h8[i] = bb;
#pragma unroll 4
        for (int c = 0; c < 64; ++c) {
            float w1 = nW1[c * 256 + t];
            float4 a0 = *(const float4*)&xa[c][0];
            float4 a1 = *(const float4*)&xa[c][4];
            h8[0] = fmaf(a0.x, w1, h8[0]); h8[1] = fmaf(a0.y, w1, h8[1]);
            h8[2] = fmaf(a0.z, w1, h8[2]); h8[3] = fmaf(a0.w, w1, h8[3]);
            h8[4] = fmaf(a1.x, w1, h8[4]); h8[5] = fmaf(a1.y, w1, h8[5]);
            h8[6] = fmaf(a1.z, w1, h8[6]); h8[7] = fmaf(a1.w, w1, h8[7]);
        }
#pragma unroll
        for (int i = 0; i < 8; ++i) hh[i][t] = fmaxf(h8[i], 0.0f);
    }
    __syncthreads();

    // stage2 + phase-B prep for frontier rows
    {
        int i = w;
        float acc = nb2[l];
#pragma unroll 8
        for (int j = 0; j < 256; ++j) acc = fmaf(hh[i][j], nW2[j * 32 + l], acc);
        float xn = xa[l][i] + acc;
        gX[(xrow0 + i) * 32 + l] = xn;
        if (isF) {
            int hr = xrow0 - OFF_F + i;
            float yk = bk[l], yv = bv[l];
#pragma unroll
            for (int c = 0; c < 32; ++c) {
                float xb = __shfl_sync(FULL, xn, c);
                yk = fmaf(xb, Wk[c * 32 + l], yk);
                yv = fmaf(xb, Wv[c * 32 + l], yv);
            }
            gYVB[hr * 32 + l] = yv;
            float hk[8];
#pragma unroll
            for (int u = 0; u < 8; ++u) hk[u] = eb1[u * 32 + l];
#pragma unroll
            for (int c = 0; c < 32; ++c) {
                float ykb = __shfl_sync(FULL, yk, c);
                const float* e1 = eW1 + (32 + c) * 256;
#pragma unroll
                for (int u = 0; u < 8; ++u) hk[u] = fmaf(ykb, e1[u * 32 + l], hk[u]);
            }
#pragma unroll
            for (int u = 0; u < 8; ++u) gHkB[hr * 256 + u * 32 + l] = hk[u];
        }
    }
}

// ---------------------------------------------------------------------------
// Phase B: split softmax, grid = 64 rows x 8 chunks of 64 j, with FUSED
// combine — the last-arriving chunk-block per row does the old B2 work.
// ---------------------------------------------------------------------------
__global__ void __launch_bounds__(256) k_mainB1(
    const float* __restrict__ disRF,
    const float* __restrict__ Wq, const float* __restrict__ bq,
    const float* __restrict__ eW1, const float* __restrict__ eW2,
    const float* __restrict__ nW1, const float* __restrict__ nb1,
    const float* __restrict__ nW2, const float* __restrict__ nb2,
    float* edgeOut, int doMLP, int cntBase) {
    __shared__ __align__(16) float hqs[256];
    __shared__ float dt[64];
    __shared__ float sc[64];
    __shared__ float redv[8];
    __shared__ float part[256];
    __shared__ float fac[8];
    __shared__ float zz[64];
    __shared__ float hh[256];
    __shared__ int isLast;

    int t = threadIdx.x, w = t >> 5, l = t & 31;
    int row = blockIdx.x >> 3, c = blockIdx.x & 7;
    int b = row >> 3;
    int jbase = b * 512 + c * 64;   // row base into gHkB / gYVB

    // x-side hq (warp w computes hq chunk w*32)
    {
        float x = gX[row * 32 + l];
        float xq = bq[l];
#pragma unroll
        for (int c2 = 0; c2 < 32; ++c2) xq = fmaf(__shfl_sync(FULL, x, c2), Wq[c2 * 32 + l], xq);
        float h = 0.0f;
#pragma unroll
        for (int c2 = 0; c2 < 32; ++c2)
            h = fmaf(__shfl_sync(FULL, xq, c2), eW1[c2 * 256 + w * 32 + l], h);
        hqs[w * 32 + l] = h;
    }
    if (t < 64) dt[t] = disRF[row * 512 + c * 64 + t];
    __syncthreads();

    float4 hq0 = *(const float4*)&hqs[4 * l];
    float4 hq1 = *(const float4*)&hqs[128 + 4 * l];
    float4 wd0 = *(const float4*)(eW1 + 64 * 256 + 4 * l);
    float4 wd1 = *(const float4*)(eW1 + 64 * 256 + 128 + 4 * l);
    float4 e20 = *(const float4*)(eW2 + 4 * l);
    float4 e21 = *(const float4*)(eW2 + 128 + 4 * l);

    // scores: warp w handles j in [w*8, w*8+8) — one butterfly group
    {
        const float4* hkp = (const float4*)(gHkB + (size_t)jbase * 256);
        int j0 = w * 8;
        float acc[8];
#pragma unroll
        for (int k = 0; k < 8; ++k) {
            int j = j0 + k;
            float4 hk0 = hkp[(size_t)j * 64 + l];
            float4 hk1 = hkp[(size_t)j * 64 + 32 + l];
            float dij = dt[j];
            acc[k] = term8(hq0, hq1, hk0, hk1, dij, wd0, wd1, e20, e21);
        }
        bfly8(acc, l);
        if (l < 8) sc[j0 + irev3(l)] = acc[0];
    }
    __syncthreads();

    // local max over 64
    float m = (t < 64) ? sc[t] : -1e30f;
    m = rmax32(m);
    if (l == 0) redv[w] = m;
    __syncthreads();
    m = redv[0];
#pragma unroll
    for (int ww = 1; ww < 8; ++ww) m = fmaxf(m, redv[ww]);
    __syncthreads();

    // exp + local sum + store e
    float e = 0.0f;
    if (t < 64) {
        e = __expf(sc[t] - m);
        sc[t] = e;
        gE[row * 512 + c * 64 + t] = e;
    }
    float s = red32(e);
    if (l == 0) redv[w] = s;
    __syncthreads();
    s = 0.0f;
#pragma unroll
    for (int ww = 0; ww < 8; ++ww) s += redv[ww];

    // partial agg over the 64-chunk (skip when final iteration: edge only)
    if (doMLP) {
        float a = 0.0f;
        for (int j = w; j < 64; j += 8) a = fmaf(sc[j], gYVB[(jbase + j) * 32 + l], a);
        part[t] = a;
        __syncthreads();
        if (t < 32) {
            float ss = 0.0f;
#pragma unroll
            for (int ww = 0; ww < 8; ++ww) ss += part[ww * 32 + t];
            gPA[(row * 8 + c) * 32 + t] = ss;
        }
    }
    if (t == 0) { gM8[row * 8 + c] = m; gS8[row * 8 + c] = s; }

    // ---- fused combine: last block per row does old-B2 work ----
    __threadfence();
    __syncthreads();
    if (t == 0) {
        int old = atomicAdd(&gCnt[cntBase + row], 1);
        isLast = (old == 7) ? 1 : 0;
    }
    __syncthreads();
    if (!isLast) return;
    __threadfence();

    if (t < 32) {
        float mv = (l < 8) ? gM8[row * 8 + l] : -1e30f;
        float sv = (l < 8) ? gS8[row * 8 + l] : 0.0f;
        float M = rmax32(mv);
        float f = (l < 8) ? __expf(mv - M) : 0.0f;
        float Z = red32(sv * f);
        if (l < 8) fac[l] = f / Z;
    }
    __syncthreads();

    if (edgeOut != nullptr) {
        for (int j = t; j < 512; j += 256)
            edgeOut[row * 512 + j] = gE[row * 512 + j] * fac[j >> 6];
    }
    if (!doMLP) return;

    if (t < 32) {
        float ss = 0.0f;
#pragma unroll
        for (int cc = 0; cc < 8; ++cc) ss = fmaf(gPA[(row * 8 + cc) * 32 + t], fac[cc], ss);
        zz[32 + t] = ss;
        zz[t] = gX[row * 32 + t];
    }
    __syncthreads();

    float acc2 = nb1[t];
#pragma unroll 8
    for (int c2 = 0; c2 < 64; ++c2) acc2 = fmaf(zz[c2], nW1[c2 * 256 + t], acc2);
    hh[t] = fmaxf(acc2, 0.0f);
    __syncthreads();
    float p = 0.0f;
#pragma unroll 8
    for (int j = w * 32; j < w * 32 + 32; ++j) p = fmaf(hh[j], nW2[j * 32 + l], p);
    part[t] = p;
    __syncthreads();
    if (t < 32) {
        float ss = nb2[t];
#pragma unroll
        for (int ww = 0; ww < 8; ++ww) ss += part[ww * 32 + t];
        gX[row * 32 + t] = zz[t] + ss;
    }
}

// ---------------------------------------------------------------------------
extern "C" void kernel_launch(void* const* d_in, const int* in_sizes, int n_in,
                              void* d_out, int out_size) {
    const float* agent_pos    = (const float*)d_in[0];
    const float* frontier_pos = (const float*)d_in[1];
    const float* past_agent   = (const float*)d_in[2];
    const float* past_goal    = (const float*)d_in[3];
    const float* dis_rp       = (const float*)d_in[4];
    const float* dis_fp       = (const float*)d_in[5];
    const float* dis_rf       = (const float*)d_in[6];
    const float* ni_W1        = (const float*)d_in[7];
    const float* ni_b1        = (const float*)d_in[8];
    const float* ni_W2        = (const float*)d_in[9];
    const float* ni_b2        = (const float*)d_in[10];
    const float* Wq           = (const float*)d_in[11];
    const float* bq           = (const float*)d_in[12];
    const float* Wk           = (const float*)d_in[13];
    const float* bk           = (const float*)d_in[14];
    const float* Wv           = (const float*)d_in[15];
    const float* bv           = (const float*)d_in[16];
    const float* nW1          = (const float*)d_in[17];
    const float* nb1          = (const float*)d_in[18];
    const float* nW2          = (const float*)d_in[19];
    const float* nb2          = (const float*)d_in[20];
    const float* eW1          = (const float*)d_in[21];
    const float* eb1          = (const float*)d_in[22];
    const float* eW2          = (const float*)d_in[23];
    float* edge = (float*)d_out;

    k_init<<<776, 256>>>(agent_pos, frontier_pos, past_agent, past_goal,
                         ni_W1, ni_b1, ni_W2, ni_b2);

    for (int b3 = 0; b3 < 3; ++b3) {
        const float* Wq_b  = Wq  + b3 * 32 * 32;
        const float* bq_b  = bq  + b3 * 32;
        const float* Wk_b  = Wk  + b3 * 32 * 32;
        const float* bk_b  = bk  + b3 * 32;
        const float* Wv_b  = Wv  + b3 * 32 * 32;
        const float* bv_b  = bv  + b3 * 32;
        const float* nW1_b = nW1 + b3 * 64 * 256;
        const float* nb1_b = nb1 + b3 * 256;
        const float* nW2_b = nW2 + b3 * 256 * 32;
        const float* nb2_b = nb2 + b3 * 32;
        const float* eW1_b = eW1 + b3 * 65 * 256;
        const float* eb1_b = eb1 + b3 * 256;
        const float* eW2_b = eW2 + b3 * 256;

        k_qkv<<<776, 256>>>(Wq_b, bq_b, Wk_b, bk_b, Wv_b, bv_b);
        k_intra<<<776, 256>>>(nW1_b, nb1_b, nW2_b, nb2_b,
                              Wk_b, bk_b, Wv_b, bv_b, eW1_b, eb1_b);
        k_mainA<<<520, 256>>>(dis_rp, dis_fp,
                              Wq_b, bq_b, Wk_b, bk_b, Wv_b, bv_b,
                              eW1_b, eb1_b, eW2_b,
                              nW1_b, nb1_b, nW2_b, nb2_b);
        float* eo = (b3 == 2) ? edge : nullptr;
        int doMLP = (b3 == 2) ? 0 : 1;
        k_mainB1<<<512, 256>>>(dis_rf, Wq_b, bq_b, eW1_b, eW2_b,
                               nW1_b, nb1_b, nW2_b, nb2_b,
                               eo, doMLP, b3 * 64);
    }
}

// round 13
// speedup vs baseline: 1.5984x; 1.0002x over previous
#include <cuda_runtime.h>

#define BB 8
#define AA 8
#define FF 512
#define HH 128
#define D  32
#define HID 256

// Row layout of fused node buffer X:
#define OFF_R  0
#define OFF_F  64
#define OFF_RH 4160
#define OFF_FH 5184
#define R_TOT  6208

#define FULL 0xffffffffu

// Static device scratch
__device__ __align__(16) float gX[R_TOT * D];
__device__ __align__(16) float gQ[R_TOT * D];
__device__ __align__(16) float gK[R_TOT * D];
__device__ __align__(16) float gV[R_TOT * D];
__device__ __align__(16) float gHk[2048 * HID];    // phase A y-side hidden (+eb1): rh [0,1024), fh [1024,2048)
__device__ __align__(16) float gYV[2048 * D];      // phase A y values
__device__ __align__(16) float gHkB[4096 * HID];   // phase B y-side (frontier)
__device__ __align__(16) float gYVB[4096 * D];
// phase-B split-softmax scratch (8 chunks of 64 j)
__device__ __align__(16) float gE[64 * 512];
__device__ float gM8[64 * 8];
__device__ float gS8[64 * 8];
__device__ __align__(16) float gPA[64 * 8 * 32];
__device__ int gCnt[192];   // 3 iterations x 64 rows, zeroed by k_init each replay

__device__ __forceinline__ float red32(float v) {
#pragma unroll
    for (int o = 16; o; o >>= 1) v += __shfl_xor_sync(FULL, v, o);
    return v;
}
__device__ __forceinline__ float rmax32(float v) {
#pragma unroll
    for (int o = 16; o; o >>= 1) v = fmaxf(v, __shfl_xor_sync(FULL, v, o));
    return v;
}
__device__ __forceinline__ float red8(float v) {
    v += __shfl_xor_sync(FULL, v, 1);
    v += __shfl_xor_sync(FULL, v, 2);
    v += __shfl_xor_sync(FULL, v, 4);
    return v;
}

// Butterfly-reduce 8 per-lane accumulators across all 32 lanes (9 shuffles).
// Afterwards lane l (l<8) holds total for index irev(l) = ((l&1)<<2)|(l&2)|((l>>2)&1).
__device__ __forceinline__ void bfly8(float (&a)[8], int l) {
    {
        bool hi = (l & 1);
#pragma unroll
        for (int k = 0; k < 4; ++k) {
            float send = hi ? a[k] : a[k + 4];
            float recv = __shfl_xor_sync(FULL, send, 1);
            a[k] = (hi ? a[k + 4] : a[k]) + recv;
        }
    }
    {
        bool hi = (l & 2);
#pragma unroll
        for (int k = 0; k < 2; ++k) {
            float send = hi ? a[k] : a[k + 2];
            float recv = __shfl_xor_sync(FULL, send, 2);
            a[k] = (hi ? a[k + 2] : a[k]) + recv;
        }
    }
    {
        bool hi = (l & 4);
        float send = hi ? a[0] : a[1];
        float recv = __shfl_xor_sync(FULL, send, 4);
        a[0] = (hi ? a[1] : a[0]) + recv;
    }
    a[0] += __shfl_xor_sync(FULL, a[0], 8);
    a[0] += __shfl_xor_sync(FULL, a[0], 16);
}
__device__ __forceinline__ int irev3(int l) {
    return ((l & 1) << 2) | (l & 2) | ((l >> 2) & 1);
}

// 8-term edge-MLP partial for one j over this lane's 8 d's
__device__ __forceinline__ float term8(const float4& hq0, const float4& hq1,
                                       const float4& a0, const float4& a1, float dij,
                                       const float4& wd0, const float4& wd1,
                                       const float4& e20, const float4& e21) {
    float acc;
    acc = fmaxf(fmaf(dij, wd0.x, hq0.x + a0.x), 0.f) * e20.x;
    acc = fmaf(fmaxf(fmaf(dij, wd0.y, hq0.y + a0.y), 0.f), e20.y, acc);
    acc = fmaf(fmaxf(fmaf(dij, wd0.z, hq0.z + a0.z), 0.f), e20.z, acc);
    acc = fmaf(fmaxf(fmaf(dij, wd0.w, hq0.w + a0.w), 0.f), e20.w, acc);
    acc = fmaf(fmaxf(fmaf(dij, wd1.x, hq1.x + a1.x), 0.f), e21.x, acc);
    acc = fmaf(fmaxf(fmaf(dij, wd1.y, hq1.y + a1.y), 0.f), e21.y, acc);
    acc = fmaf(fmaxf(fmaf(dij, wd1.z, hq1.z + a1.z), 0.f), e21.z, acc);
    acc = fmaf(fmaxf(fmaf(dij, wd1.w, hq1.w + a1.w), 0.f), e21.w, acc);
    return acc;
}

// ---------------------------------------------------------------------------
// Node-init MLP, warp-per-row (8 rows per block) + counter reset
// ---------------------------------------------------------------------------
__global__ void __launch_bounds__(256) k_init(
    const float* __restrict__ ap, const float* __restrict__ fp,
    const float* __restrict__ pa, const float* __restrict__ pg,
    const float* __restrict__ W1, const float* __restrict__ b1,
    const float* __restrict__ W2, const float* __restrict__ b2) {
    __shared__ float hw[8][256];
    int w = threadIdx.x >> 5, l = threadIdx.x & 31;
    if (blockIdx.x == 0 && threadIdx.x < 192) gCnt[threadIdx.x] = 0;
    int r = blockIdx.x * 8 + w;
    const float* src;
    if (r < OFF_F)        src = ap + r * 3;
    else if (r < OFF_RH)  src = fp + (r - OFF_F) * 3;
    else if (r < OFF_FH)  src = pa + (r - OFF_RH) * 3;
    else                  src = pg + (r - OFF_FH) * 3;
    float x0 = src[0], x1 = src[1], x2 = src[2];
#pragma unroll
    for (int u = 0; u < 8; ++u) {
        int d = u * 32 + l;
        float h = fmaf(x0, W1[d], fmaf(x1, W1[256 + d], fmaf(x2, W1[512 + d], b1[d])));
        hw[w][d] = fmaxf(h, 0.0f);
    }
    __syncwarp();
    float acc = b2[l];
#pragma unroll 8
    for (int j = 0; j < 256; ++j) acc = fmaf(hw[w][j], W2[j * 32 + l], acc);
    gX[r * 32 + l] = acc;
}

// ---------------------------------------------------------------------------
// QKV projections, warp-per-row
// ---------------------------------------------------------------------------
__global__ void __launch_bounds__(256) k_qkv(
    const float* __restrict__ Wq, const float* __restrict__ bq,
    const float* __restrict__ Wk, const float* __restrict__ bk,
    const float* __restrict__ Wv, const float* __restrict__ bv) {
    int w = threadIdx.x >> 5, l = threadIdx.x & 31;
    int r = blockIdx.x * 8 + w;
    float x = gX[r * 32 + l];
    float aq = bq[l], ak = bk[l], av = bv[l];
#pragma unroll
    for (int c = 0; c < 32; ++c) {
        float xb = __shfl_sync(FULL, x, c);
        aq = fmaf(xb, Wq[c * 32 + l], aq);
        ak = fmaf(xb, Wk[c * 32 + l], ak);
        av = fmaf(xb, Wv[c * 32 + l], av);
    }
    gQ[r * 32 + l] = aq; gK[r * 32 + l] = ak; gV[r * 32 + l] = av;
}

// ---------------------------------------------------------------------------
// Intra attention, TI=8 rows per block, + fused y-side prep for rh/fh rows
// Score-loop k4 LDG software-pipelined (R7-proven pattern).
// blocks: [0,8) robot  [8,520) frontier  [520,648) rh  [648,776) fh
// ---------------------------------------------------------------------------
__global__ void __launch_bounds__(256) k_intra(
    const float* __restrict__ nW1, const float* __restrict__ nb1,
    const float* __restrict__ nW2, const float* __restrict__ nb2,
    const float* __restrict__ Wk, const float* __restrict__ bk,
    const float* __restrict__ Wv, const float* __restrict__ bv,
    const float* __restrict__ eW1, const float* __restrict__ eb1) {
    __shared__ __align__(16) float qs[8][32];
    __shared__ float sc[8][512];
    __shared__ float partA[8][8][32];
    __shared__ __align__(16) float xa[64][8];
    __shared__ float hh[8][256];
    __shared__ float inv[8];

    int t = threadIdx.x, w = t >> 5, l = t & 31;
    int blk = blockIdx.x;
    int base, N, r0;
    if (blk < 8)        { base = blk * 8; N = 8; r0 = base; }
    else if (blk < 520) { int f = blk - 8;   int b = f >> 6, tl = f & 63; base = OFF_F  + b * 512; N = 512; r0 = base + tl * 8; }
    else if (blk < 648) { int g = blk - 520; int b = g >> 4, tl = g & 15; base = OFF_RH + b * 128; N = 128; r0 = base + tl * 8; }
    else                { int g = blk - 648; int b = g >> 4, tl = g & 15; base = OFF_FH + b * 128; N = 128; r0 = base + tl * 8; }

    qs[w][l] = gQ[(r0 + w) * 32 + l];
    __syncthreads();

    // scores: subwarp-8 groups, 4 j per warp in flight, k4 LDG pipelined
    int sl = l & 7, slot = w * 4 + (l >> 3);
    {
        float4 k4 = make_float4(0.f, 0.f, 0.f, 0.f);
        if (slot < N) k4 = *(const float4*)(gK + (base + slot) * 32 + sl * 4);
        for (int jj = slot; jj < N; jj += 32) {
            float4 nk4 = k4;
            if (jj + 32 < N) nk4 = *(const float4*)(gK + (base + jj + 32) * 32 + sl * 4);
#pragma unroll
            for (int i = 0; i < 8; ++i) {
                float4 q4 = *(const float4*)&qs[i][sl * 4];
                float acc = q4.x * k4.x + q4.y * k4.y + q4.z * k4.z + q4.w * k4.w;
                acc = red8(acc);
                if (sl == 0) sc[i][jj] = acc;
            }
            k4 = nk4;
        }
    }
    __syncthreads();

    // softmax: warp-per-i
    {
        int i = w;
        float m = -1e30f;
        for (int j = l; j < N; j += 32) m = fmaxf(m, sc[i][j]);
        m = rmax32(m);
        float s = 0.0f;
        for (int j = l; j < N; j += 32) { float e = __expf(sc[i][j] - m); sc[i][j] = e; s += e; }
        s = red32(s);
        if (l == 0) inv[i] = 1.0f / s;
    }
    __syncthreads();

    // agg: warps split j, 8 accumulators
    {
        float ac[8];
#pragma unroll
        for (int i = 0; i < 8; ++i) ac[i] = 0.0f;
        for (int j = w; j < N; j += 8) {
            float v = gV[(base + j) * 32 + l];
#pragma unroll
            for (int i = 0; i < 8; ++i) ac[i] = fmaf(sc[i][j], v, ac[i]);
        }
#pragma unroll
        for (int i = 0; i < 8; ++i) partA[w][i][l] = ac[i];
    }
    __syncthreads();
    {
        int i = w;
        float s = 0.0f;
#pragma unroll
        for (int ww = 0; ww < 8; ++ww) s += partA[ww][i][l];
        xa[32 + l][i] = s * inv[i];
        xa[l][i] = gX[(r0 + i) * 32 + l];
    }
    __syncthreads();

    // node MLP stage1
    {
        float h8[8];
        float bb = nb1[t];
#pragma unroll
        for (int i = 0; i < 8; ++i) h8[i] = bb;
#pragma unroll 4
        for (int c = 0; c < 64; ++c) {
            float w1 = nW1[c * 256 + t];
            float4 a0 = *(const float4*)&xa[c][0];
            float4 a1 = *(const float4*)&xa[c][4];
            h8[0] = fmaf(a0.x, w1, h8[0]); h8[1] = fmaf(a0.y, w1, h8[1]);
            h8[2] = fmaf(a0.z, w1, h8[2]); h8[3] = fmaf(a0.w, w1, h8[3]);
            h8[4] = fmaf(a1.x, w1, h8[4]); h8[5] = fmaf(a1.y, w1, h8[5]);
            h8[6] = fmaf(a1.z, w1, h8[6]); h8[7] = fmaf(a1.w, w1, h8[7]);
        }
#pragma unroll
        for (int i = 0; i < 8; ++i) hh[i][t] = fmaxf(h8[i], 0.0f);
    }
    __syncthreads();

    // stage2: warp-per-i output + residual + fused y-prep
    {
        int i = w;
        float acc = nb2[l];
#pragma unroll 8
        for (int j = 0; j < 256; ++j) acc = fmaf(hh[i][j], nW2[j * 32 + l], acc);
        float xn = xa[l][i] + acc;
        int r = r0 + i;
        gX[r * 32 + l] = xn;
        if (r >= OFF_RH) {  // rh/fh rows: emit hk, yv for phase A
            int hr = r - OFF_RH;
            float yk = bk[l], yv = bv[l];
#pragma unroll
            for (int c = 0; c < 32; ++c) {
                float xb = __shfl_sync(FULL, xn, c);
                yk = fmaf(xb, Wk[c * 32 + l], yk);
                yv = fmaf(xb, Wv[c * 32 + l], yv);
            }
            gYV[hr * 32 + l] = yv;
            float hk[8];
#pragma unroll
            for (int u = 0; u < 8; ++u) hk[u] = eb1[u * 32 + l];
#pragma unroll
            for (int c = 0; c < 32; ++c) {
                float ykb = __shfl_sync(FULL, yk, c);
                const float* e1 = eW1 + (32 + c) * 256;
#pragma unroll
                for (int u = 0; u < 8; ++u) hk[u] = fmaf(ykb, e1[u * 32 + l], hk[u]);
            }
#pragma unroll
            for (int u = 0; u < 8; ++u) gHk[hr * 256 + u * 32 + l] = hk[u];
        }
    }
}

// ---------------------------------------------------------------------------
// Inter phase A: j partitioned across warps, butterfly 8-i reduction,
// software-pipelined hk loads (j+1 prefetched during j's compute).
// blocks: [0,8) robot-vs-rh  [8,520) frontier-vs-fh
// ---------------------------------------------------------------------------
__global__ void __launch_bounds__(256, 2) k_mainA(
    const float* __restrict__ disRP, const float* __restrict__ disFP,
    const float* __restrict__ Wq, const float* __restrict__ bq,
    const float* __restrict__ Wk, const float* __restrict__ bk,
    const float* __restrict__ Wv, const float* __restrict__ bv,
    const float* __restrict__ eW1, const float* __restrict__ eb1,
    const float* __restrict__ eW2,
    const float* __restrict__ nW1, const float* __restrict__ nb1,
    const float* __restrict__ nW2, const float* __restrict__ nb2) {
    __shared__ __align__(16) float hqs[8][256];
    __shared__ float dt[1024];
    __shared__ float sc[8][128];
    __shared__ float partA[8][8][32];
    __shared__ __align__(16) float xa[64][8];
    __shared__ float hh[8][256];
    __shared__ float inv[8];

    int t = threadIdx.x, w = t >> 5, l = t & 31;
    int blk = blockIdx.x;
    int xrow0, hkbase, isF;
    const float* disrow;
    if (blk < 8) { xrow0 = blk * 8; hkbase = blk * 128; isF = 0; disrow = disRP + blk * 8 * 128; }
    else {
        int f = blk - 8; int b = f >> 6, tl = f & 63;
        xrow0 = OFF_F + b * 512 + tl * 8; hkbase = 1024 + b * 128; isF = 1;
        disrow = disFP + (b * 512 + tl * 8) * 128;
    }

    // x-side: xq = X@Wq+bq ; hq = xq@eW1[0:32]  (warp-per-i, layout d=u*32+l)
    {
        float x = gX[(xrow0 + w) * 32 + l];
        float xq = bq[l];
#pragma unroll
        for (int c = 0; c < 32; ++c) xq = fmaf(__shfl_sync(FULL, x, c), Wq[c * 32 + l], xq);
        float hq[8];
#pragma unroll
        for (int u = 0; u < 8; ++u) hq[u] = 0.0f;
#pragma unroll
        for (int c = 0; c < 32; ++c) {
            float xqb = __shfl_sync(FULL, xq, c);
            const float* e1 = eW1 + c * 256;
#pragma unroll
            for (int u = 0; u < 8; ++u) hq[u] = fmaf(xqb, e1[u * 32 + l], hq[u]);
        }
#pragma unroll
        for (int u = 0; u < 8; ++u) hqs[w][u * 32 + l] = hq[u];
    }
    for (int idx = t; idx < 1024; idx += 256) dt[idx] = disrow[idx];
    __syncthreads();

    // lane-resident weight slices: d = 4l..4l+3 and 128+4l..128+4l+3
    float4 wd0 = *(const float4*)(eW1 + 64 * 256 + 4 * l);
    float4 wd1 = *(const float4*)(eW1 + 64 * 256 + 128 + 4 * l);
    float4 e20 = *(const float4*)(eW2 + 4 * l);
    float4 e21 = *(const float4*)(eW2 + 128 + 4 * l);

    // scores: warp w handles j in [16w, 16w+16); hk loads software-pipelined
    {
        const float4* hkp = (const float4*)(gHk + (size_t)hkbase * 256);
        int j0 = w * 16;
        float4 hk0 = hkp[(size_t)j0 * 64 + l];
        float4 hk1 = hkp[(size_t)j0 * 64 + 32 + l];
        for (int jj = 0; jj < 16; ++jj) {
            int j = j0 + jj;
            float4 nk0, nk1;
            if (jj < 15) {
                nk0 = hkp[(size_t)(j + 1) * 64 + l];
                nk1 = hkp[(size_t)(j + 1) * 64 + 32 + l];
            }
            float dj[8];
#pragma unroll
            for (int i = 0; i < 8; ++i) dj[i] = dt[i * 128 + j];
            float acc[8];
#pragma unroll
            for (int i = 0; i < 8; ++i) {
                float4 hq0 = *(const float4*)&hqs[i][4 * l];
                float4 hq1 = *(const float4*)&hqs[i][128 + 4 * l];
                acc[i] = term8(hq0, hq1, hk0, hk1, dj[i], wd0, wd1, e20, e21);
            }
            bfly8(acc, l);
            if (l < 8) sc[irev3(l)][j] = acc[0];
            hk0 = nk0; hk1 = nk1;
        }
    }
    __syncthreads();

    // softmax warp-per-i
    {
        int i = w;
        float m = -1e30f;
#pragma unroll
        for (int k = 0; k < 4; ++k) m = fmaxf(m, sc[i][l + 32 * k]);
        m = rmax32(m);
        float s = 0.0f;
#pragma unroll
        for (int k = 0; k < 4; ++k) {
            float e = __expf(sc[i][l + 32 * k] - m);
            sc[i][l + 32 * k] = e; s += e;
        }
        s = red32(s);
        if (l == 0) inv[i] = 1.0f / s;
    }
    __syncthreads();

    // agg
    {
        float ac[8];
#pragma unroll
        for (int i = 0; i < 8; ++i) ac[i] = 0.0f;
        for (int j = w; j < 128; j += 8) {
            float v = gYV[(hkbase + j) * 32 + l];
#pragma unroll
            for (int i = 0; i < 8; ++i) ac[i] = fmaf(sc[i][j], v, ac[i]);
        }
#pragma unroll
        for (int i = 0; i < 8; ++i) partA[w][i][l] = ac[i];
    }
    __syncthreads();
    {
        int i = w;
        float s = 0.0f;
#pragma unroll
        for (int ww = 0; ww < 8; ++ww) s += partA[ww][i][l];
        xa[32 + l][i] = s * inv[i];
        xa[l][i] = gX[(xrow0 + i) * 32 + l];
    }
    __syncthreads();

    // node MLP stage1
    {
        float h8[8];
        float bb = nb1[t];
#pragma unroll
        for (int i = 0; i < 8; ++i) h8[i] = bb;
#pragma unroll 4
        for (int c = 0; c < 64; ++c) {
            float w1 = nW1[c * 256 + t];
            float4 a0 = *(const float4*)&xa[c][0];
            float4 a1 = *(const float4*)&xa[c][4];
            h8[0] = fmaf(a0.x, w1, h8[0]); h8[1] = fmaf(a0.y, w1, h8[1]);
            h8[2] = fmaf(a0.z, w1, h8[2]); h8[3] = fmaf(a0.w, w1, h8[3]);
            h8[4] = fmaf(a1.x, w1, h8[4]); h8[5] = fmaf(a1.y, w1, h8[5]);
            h8[6] = fmaf(a1.z, w1, h8[6]); h8[7] = fmaf(a1.w, w1, h8[7]);
        }
#pragma unroll
        for (int i = 0; i < 8; ++i) hh[i][t] = fmaxf(h8[i], 0.0f);
    }
    __syncthreads();

    // stage2 + phase-B prep for frontier rows
    {
        int i = w;
        float acc = nb2[l];
#pragma unroll 8
        for (int j = 0; j < 256; ++j) acc = fmaf(hh[i][j], nW2[j * 32 + l], acc);
        float xn = xa[l][i] + acc;
        gX[(xrow0 + i) * 32 + l] = xn;
        if (isF) {
            int hr = xrow0 - OFF_F + i;
            float yk = bk[l], yv = bv[l];
#pragma unroll
            for (int c = 0; c < 32; ++c) {
                float xb = __shfl_sync(FULL, xn, c);
                yk = fmaf(xb, Wk[c * 32 + l], yk);
                yv = fmaf(xb, Wv[c * 32 + l], yv);
            }
            gYVB[hr * 32 + l] = yv;
            float hk[8];
#pragma unroll
            for (int u = 0; u < 8; ++u) hk[u] = eb1[u * 32 + l];
#pragma unroll
            for (int c = 0; c < 32; ++c) {
                float ykb = __shfl_sync(FULL, yk, c);
                const float* e1 = eW1 + (32 + c) * 256;
#pragma unroll
                for (int u = 0; u < 8; ++u) hk[u] = fmaf(ykb, e1[u * 32 + l], hk[u]);
            }
#pragma unroll
            for (int u = 0; u < 8; ++u) gHkB[hr * 256 + u * 32 + l] = hk[u];
        }
    }
}

// ---------------------------------------------------------------------------
// Phase B: split softmax, grid = 64 rows x 8 chunks of 64 j, with FUSED
// combine — the last-arriving chunk-block per row does the old B2 work.
// ---------------------------------------------------------------------------
__global__ void __launch_bounds__(256) k_mainB1(
    const float* __restrict__ disRF,
    const float* __restrict__ Wq, const float* __restrict__ bq,
    const float* __restrict__ eW1, const float* __restrict__ eW2,
    const float* __restrict__ nW1, const float* __restrict__ nb1,
    const float* __restrict__ nW2, const float* __restrict__ nb2,
    float* edgeOut, int doMLP, int cntBase) {
    __shared__ __align__(16) float hqs[256];
    __shared__ float dt[64];
    __shared__ float sc[64];
    __shared__ float redv[8];
    __shared__ float part[256];
    __shared__ float fac[8];
    __shared__ float zz[64];
    __shared__ float hh[256];
    __shared__ int isLast;

    int t = threadIdx.x, w = t >> 5, l = t & 31;
    int row = blockIdx.x >> 3, c = blockIdx.x & 7;
    int b = row >> 3;
    int jbase = b * 512 + c * 64;   // row base into gHkB / gYVB

    // x-side hq (warp w computes hq chunk w*32)
    {
        float x = gX[row * 32 + l];
        float xq = bq[l];
#pragma unroll
        for (int c2 = 0; c2 < 32; ++c2) xq = fmaf(__shfl_sync(FULL, x, c2), Wq[c2 * 32 + l], xq);
        float h = 0.0f;
#pragma unroll
        for (int c2 = 0; c2 < 32; ++c2)
            h = fmaf(__shfl_sync(FULL, xq, c2), eW1[c2 * 256 + w * 32 + l], h);
        hqs[w * 32 + l] = h;
    }
    if (t < 64) dt[t] = disRF[row * 512 + c * 64 + t];
    __syncthreads();

    float4 hq0 = *(const float4*)&hqs[4 * l];
    float4 hq1 = *(const float4*)&hqs[128 + 4 * l];
    float4 wd0 = *(const float4*)(eW1 + 64 * 256 + 4 * l);
    float4 wd1 = *(const float4*)(eW1 + 64 * 256 + 128 + 4 * l);
    float4 e20 = *(const float4*)(eW2 + 4 * l);
    float4 e21 = *(const float4*)(eW2 + 128 + 4 * l);

    // scores: warp w handles j in [w*8, w*8+8) — one butterfly group
    {
        const float4* hkp = (const float4*)(gHkB + (size_t)jbase * 256);
        int j0 = w * 8;
        float acc[8];
#pragma unroll
        for (int k = 0; k < 8; ++k) {
            int j = j0 + k;
            float4 hk0 = hkp[(size_t)j * 64 + l];
            float4 hk1 = hkp[(size_t)j * 64 + 32 + l];
            float dij = dt[j];
            acc[k] = term8(hq0, hq1, hk0, hk1, dij, wd0, wd1, e20, e21);
        }
        bfly8(acc, l);
        if (l < 8) sc[j0 + irev3(l)] = acc[0];
    }
    __syncthreads();

    // local max over 64
    float m = (t < 64) ? sc[t] : -1e30f;
    m = rmax32(m);
    if (l == 0) redv[w] = m;
    __syncthreads();
    m = redv[0];
#pragma unroll
    for (int ww = 1; ww < 8; ++ww) m = fmaxf(m, redv[ww]);
    __syncthreads();

    // exp + local sum + store e
    float e = 0.0f;
    if (t < 64) {
        e = __expf(sc[t] - m);
        sc[t] = e;
        gE[row * 512 + c * 64 + t] = e;
    }
    float s = red32(e);
    if (l == 0) redv[w] = s;
    __syncthreads();
    s = 0.0f;
#pragma unroll
    for (int ww = 0; ww < 8; ++ww) s += redv[ww];

    // partial agg over the 64-chunk (skip when final iteration: edge only)
    if (doMLP) {
        float a = 0.0f;
        for (int j = w; j < 64; j += 8) a = fmaf(sc[j], gYVB[(jbase + j) * 32 + l], a);
        part[t] = a;
        __syncthreads();
        if (t < 32) {
            float ss = 0.0f;
#pragma unroll
            for (int ww = 0; ww < 8; ++ww) ss += part[ww * 32 + t];
            gPA[(row * 8 + c) * 32 + t] = ss;
        }
    }
    if (t == 0) { gM8[row * 8 + c] = m; gS8[row * 8 + c] = s; }

    // ---- fused combine: last block per row does old-B2 work ----
    __threadfence();
    __syncthreads();
    if (t == 0) {
        int old = atomicAdd(&gCnt[cntBase + row], 1);
        isLast = (old == 7) ? 1 : 0;
    }
    __syncthreads();
    if (!isLast) return;
    __threadfence();

    if (t < 32) {
        float mv = (l < 8) ? gM8[row * 8 + l] : -1e30f;
        float sv = (l < 8) ? gS8[row * 8 + l] : 0.0f;
        float M = rmax32(mv);
        float f = (l < 8) ? __expf(mv - M) : 0.0f;
        float Z = red32(sv * f);
        if (l < 8) fac[l] = f / Z;
    }
    __syncthreads();

    if (edgeOut != nullptr) {
        for (int j = t; j < 512; j += 256)
            edgeOut[row * 512 + j] = gE[row * 512 + j] * fac[j >> 6];
    }
    if (!doMLP) return;

    if (t < 32) {
        float ss = 0.0f;
#pragma unroll
        for (int cc = 0; cc < 8; ++cc) ss = fmaf(gPA[(row * 8 + cc) * 32 + t], fac[cc], ss);
        zz[32 + t] = ss;
        zz[t] = gX[row * 32 + t];
    }
    __syncthreads();

    float acc2 = nb1[t];
#pragma unroll 8
    for (int c2 = 0; c2 < 64; ++c2) acc2 = fmaf(zz[c2], nW1[c2 * 256 + t], acc2);
    hh[t] = fmaxf(acc2, 0.0f);
    __syncthreads();
    float p = 0.0f;
#pragma unroll 8
    for (int j = w * 32; j < w * 32 + 32; ++j) p = fmaf(hh[j], nW2[j * 32 + l], p);
    part[t] = p;
    __syncthreads();
    if (t < 32) {
        float ss = nb2[t];
#pragma unroll
        for (int ww = 0; ww < 8; ++ww) ss += part[ww * 32 + t];
        gX[row * 32 + t] = zz[t] + ss;
    }
}

// ---------------------------------------------------------------------------
extern "C" void kernel_launch(void* const* d_in, const int* in_sizes, int n_in,
                              void* d_out, int out_size) {
    const float* agent_pos    = (const float*)d_in[0];
    const float* frontier_pos = (const float*)d_in[1];
    const float* past_agent   = (const float*)d_in[2];
    const float* past_goal    = (const float*)d_in[3];
    const float* dis_rp       = (const float*)d_in[4];
    const float* dis_fp       = (const float*)d_in[5];
    const float* dis_rf       = (const float*)d_in[6];
    const float* ni_W1        = (const float*)d_in[7];
    const float* ni_b1        = (const float*)d_in[8];
    const float* ni_W2        = (const float*)d_in[9];
    const float* ni_b2        = (const float*)d_in[10];
    const float* Wq           = (const float*)d_in[11];
    const float* bq           = (const float*)d_in[12];
    const float* Wk           = (const float*)d_in[13];
    const float* bk           = (const float*)d_in[14];
    const float* Wv           = (const float*)d_in[15];
    const float* bv           = (const float*)d_in[16];
    const float* nW1          = (const float*)d_in[17];
    const float* nb1          = (const float*)d_in[18];
    const float* nW2          = (const float*)d_in[19];
    const float* nb2          = (const float*)d_in[20];
    const float* eW1          = (const float*)d_in[21];
    const float* eb1          = (const float*)d_in[22];
    const float* eW2          = (const float*)d_in[23];
    float* edge = (float*)d_out;

    k_init<<<776, 256>>>(agent_pos, frontier_pos, past_agent, past_goal,
                         ni_W1, ni_b1, ni_W2, ni_b2);

    for (int b3 = 0; b3 < 3; ++b3) {
        const float* Wq_b  = Wq  + b3 * 32 * 32;
        const float* bq_b  = bq  + b3 * 32;
        const float* Wk_b  = Wk  + b3 * 32 * 32;
        const float* bk_b  = bk  + b3 * 32;
        const float* Wv_b  = Wv  + b3 * 32 * 32;
        const float* bv_b  = bv  + b3 * 32;
        const float* nW1_b = nW1 + b3 * 64 * 256;
        const float* nb1_b = nb1 + b3 * 256;
        const float* nW2_b = nW2 + b3 * 256 * 32;
        const float* nb2_b = nb2 + b3 * 32;
        const float* eW1_b = eW1 + b3 * 65 * 256;
        const float* eb1_b = eb1 + b3 * 256;
        const float* eW2_b = eW2 + b3 * 256;

        k_qkv<<<776, 256>>>(Wq_b, bq_b, Wk_b, bk_b, Wv_b, bv_b);
        k_intra<<<776, 256>>>(nW1_b, nb1_b, nW2_b, nb2_b,
                              Wk_b, bk_b, Wv_b, bv_b, eW1_b, eb1_b);
        k_mainA<<<520, 256>>>(dis_rp, dis_fp,
                              Wq_b, bq_b, Wk_b, bk_b, Wv_b, bv_b,
                              eW1_b, eb1_b, eW2_b,
                              nW1_b, nb1_b, nW2_b, nb2_b);
        float* eo = (b3 == 2) ? edge : nullptr;
        int doMLP = (b3 == 2) ? 0 : 1;
        k_mainB1<<<512, 256>>>(dis_rf, Wq_b, bq_b, eW1_b, eW2_b,
                               nW1_b, nb1_b, nW2_b, nb2_b,
                               eo, doMLP, b3 * 64);
    }
}